// round 11
// baseline (speedup 1.0000x reference)
#include <cuda_runtime.h>
#include <cuda_bf16.h>
#include <math.h>

#define B_  256
#define T_  256
#define E_  64
#define N_  512
#define V_  128
#define G4  2048   // 4*N
#define NBLK 128

#define KS_BF 520   // Whs stride in bf16: [col][k], padded
#define KS_W  260
#define HA_BF 136   // hA stride in bf16: [row][k] per 128-k chunk, padded (136%64=8 -> bank-safe)
#define HA_W  68
#define Z_STRIDE 68 // z-exchange float stride

// SMEM byte offsets (recurrence)
#define OFF_WHI 0
#define OFF_WLO (64 * KS_BF * 2)                 // 66560
#define OFF_HA  (2 * 64 * KS_BF * 2)             // 133120
#define HA_BYTES (64 * HA_BF * 2)                // 17408
#define SMEM_TOTAL_LSTM (OFF_HA + 4 * HA_BYTES)  // 202752

// GEMM kernels (input/out): 4 planes of [128][36 words]
#define GW 36
#define PLANE (128 * GW)
#define SMEM_GEMM (4 * PLANE * 4)                 // 73728 bytes

// ---- scratch (static device memory; no allocations) ----
__device__ float g_xz[(size_t)T_ * B_ * G4];   // [T,B,4N] input projections (+bias)
__device__ float g_hs[(size_t)T_ * B_ * N_];   // [T,B,N] hidden states for final dense
__device__ float g_h[2][B_ * N_];              // ping-pong h
__device__ unsigned g_flags[NBLK * 32];        // grid barrier flags, 128B-padded

// ---------------------------------------------------------------------------
__device__ __forceinline__ float sigf(float x) {
    return __fdividef(1.f, 1.f + __expf(-x));
}

// overflow-safe fast tanh
__device__ __forceinline__ float tanhf_fast(float x) {
    float t = __expf(-2.f * fabsf(x));
    float r = __fdividef(1.f - t, 1.f + t);
    return copysignf(r, x);
}

__device__ __forceinline__ void mma_bf16(float* d, const unsigned* a, const unsigned* b) {
    asm volatile(
        "mma.sync.aligned.m16n8k16.row.col.f32.bf16.bf16.f32 "
        "{%0,%1,%2,%3}, {%4,%5,%6,%7}, {%8,%9}, {%0,%1,%2,%3};"
        : "+f"(d[0]), "+f"(d[1]), "+f"(d[2]), "+f"(d[3])
        : "r"(a[0]), "r"(a[1]), "r"(a[2]), "r"(a[3]), "r"(b[0]), "r"(b[1]));
}

__device__ __forceinline__ void bf16_split(float x, __nv_bfloat16& hi, __nv_bfloat16& lo) {
    hi = __float2bfloat16(x);
    lo = __float2bfloat16(x - __bfloat162float(hi));
}

__device__ __forceinline__ unsigned pack_bf2(__nv_bfloat16 lo, __nv_bfloat16 hi) {
    unsigned short ul = __bfloat16_as_ushort(lo);
    unsigned short uh = __bfloat16_as_ushort(hi);
    return (unsigned)ul | ((unsigned)uh << 16);
}

__device__ __forceinline__ void split4(float4 v, uint2& hw, uint2& lw) {
    __nv_bfloat16 h0, l0, h1, l1, h2, l2, h3, l3;
    bf16_split(v.x, h0, l0); bf16_split(v.y, h1, l1);
    bf16_split(v.z, h2, l2); bf16_split(v.w, h3, l3);
    hw = make_uint2(pack_bf2(h0, h1), pack_bf2(h2, h3));
    lw = make_uint2(pack_bf2(l0, l1), pack_bf2(l2, l3));
}

extern __shared__ char smem_raw[];

// ---------------------------------------------------------------------------
// init: load h_0, reset barrier flags (part of the graph -> replay-safe)
// ---------------------------------------------------------------------------
__global__ void init_kernel(const float* __restrict__ h0) {
    int i = blockIdx.x * blockDim.x + threadIdx.x;
    if (i < B_ * N_) g_h[0][i] = h0[i];
    if (i < NBLK)    g_flags[i * 32] = 0u;
}

// ---------------------------------------------------------------------------
// bf16x2 tensor-core GEMM core for input/out GEMMs
// ---------------------------------------------------------------------------
__device__ __forceinline__ void gemm_chunk(const unsigned* AhiW, const unsigned* AloW,
                                           const unsigned* BhiW, const unsigned* BloW,
                                           int wr, int wc, int g4r, int lk,
                                           float acc[2][8][4]) {
#pragma unroll
    for (int k16 = 0; k16 < 4; k16++) {
        unsigned aHi[2][4], aLo[2][4];
#pragma unroll
        for (int f = 0; f < 2; f++) {
            int aw = (wr + f * 16 + g4r) * GW + lk + k16 * 8;
            aHi[f][0] = AhiW[aw];          aHi[f][1] = AhiW[aw + 8 * GW];
            aHi[f][2] = AhiW[aw + 4];      aHi[f][3] = AhiW[aw + 8 * GW + 4];
            aLo[f][0] = AloW[aw];          aLo[f][1] = AloW[aw + 8 * GW];
            aLo[f][2] = AloW[aw + 4];      aLo[f][3] = AloW[aw + 8 * GW + 4];
        }
#pragma unroll
        for (int sub = 0; sub < 8; sub++) {
            int col = wc + sub * 8 + g4r;
            int bw  = col * GW + lk + k16 * 8;
            unsigned bHi[2], bLo[2];
            bHi[0] = BhiW[bw]; bHi[1] = BhiW[bw + 4];
            bLo[0] = BloW[bw]; bLo[1] = BloW[bw + 4];
#pragma unroll
            for (int f = 0; f < 2; f++) {
                mma_bf16(acc[f][sub], aHi[f], bHi);
                mma_bf16(acc[f][sub], aHi[f], bLo);
                mma_bf16(acc[f][sub], aLo[f], bHi);
            }
        }
    }
}

// ---------------------------------------------------------------------------
// Kernel A (tensor): xz[r][g] = bias[g] + sum_e emb[X[b][t]][e] * Wx[e][g]
// ---------------------------------------------------------------------------
__global__ void __launch_bounds__(256)
input_gemm_tc(const int*   __restrict__ X,
              const float* __restrict__ emb,
              const float* __restrict__ Wx,
              const float* __restrict__ bias) {
    unsigned* AhiW = (unsigned*)smem_raw;
    unsigned* AloW = AhiW + PLANE;
    unsigned* BhiW = AloW + PLANE;
    unsigned* BloW = BhiW + PLANE;
    __shared__ int xid[128];

    const int tid  = threadIdx.x;
    const int r0   = blockIdx.y * 128;
    const int g0   = blockIdx.x * 128;
    const int lane = tid & 31;
    const int wid  = tid >> 5;
    const int wr   = (wid & 3) * 32;
    const int wc   = (wid >> 2) * 64;
    const int g4r  = lane >> 2;
    const int lk   = lane & 3;
    const int lx2  = lk * 2;

    if (tid < 128) {
        int r = r0 + tid;
        xid[tid] = X[(r & 255) * T_ + (r >> 8)];
    }
    __syncthreads();

    {
        int row = tid >> 1;
        const float* src = emb + (size_t)xid[row] * E_;
        int qb = (tid & 1) * 8;
#pragma unroll
        for (int q = 0; q < 8; q++) {
            float4 v = *(const float4*)(src + (qb + q) * 4);
            uint2 hw, lw;
            split4(v, hw, lw);
            int widx = row * GW + (qb + q) * 2;
            *(uint2*)(AhiW + widx) = hw;
            *(uint2*)(AloW + widx) = lw;
        }
    }
    {
        int c = tid & 127, khalf = tid >> 7;
#pragma unroll
        for (int kk = 0; kk < 16; kk++) {
            int k0 = khalf * 32 + kk * 2;
            float a = Wx[(size_t)k0 * G4 + g0 + c];
            float b = Wx[(size_t)(k0 + 1) * G4 + g0 + c];
            __nv_bfloat16 ha, la, hb, lb;
            bf16_split(a, ha, la); bf16_split(b, hb, lb);
            int widx = c * GW + khalf * 16 + kk;
            BhiW[widx] = pack_bf2(ha, hb);
            BloW[widx] = pack_bf2(la, lb);
        }
    }
    __syncthreads();

    float acc[2][8][4];
#pragma unroll
    for (int f = 0; f < 2; f++)
#pragma unroll
        for (int s = 0; s < 8; s++)
#pragma unroll
            for (int i = 0; i < 4; i++) acc[f][s][i] = 0.f;

    gemm_chunk(AhiW, AloW, BhiW, BloW, wr, wc, g4r, lk, acc);

#pragma unroll
    for (int f = 0; f < 2; f++) {
        int rlo = r0 + wr + f * 16 + g4r;
#pragma unroll
        for (int sub = 0; sub < 8; sub++) {
            int g = g0 + wc + sub * 8 + lx2;
            float2 bb = *(const float2*)(bias + g);
            *(float2*)(g_xz + (size_t)rlo * G4 + g) =
                make_float2(acc[f][sub][0] + bb.x, acc[f][sub][1] + bb.y);
            *(float2*)(g_xz + (size_t)(rlo + 8) * G4 + g) =
                make_float2(acc[f][sub][2] + bb.x, acc[f][sub][3] + bb.y);
        }
    }
}

// ---------------------------------------------------------------------------
// Persistent LSTM recurrence (R9 base), K-chunk widened 64 -> 128:
//  4 staging iterations/step instead of 8 (half the syncs, longer MMA runs).
// ---------------------------------------------------------------------------
__global__ void __launch_bounds__(256, 1)
lstm_persistent(const float* __restrict__ Wh, const float* __restrict__ c0) {
    __nv_bfloat16* WhHi = (__nv_bfloat16*)(smem_raw + OFF_WHI);
    __nv_bfloat16* WhLo = (__nv_bfloat16*)(smem_raw + OFF_WLO);
    const unsigned* WhHiW = (const unsigned*)WhHi;
    const unsigned* WhLoW = (const unsigned*)WhLo;

    char* hBase = smem_raw + OFF_HA;   // buf0: hi,lo ; buf1: hi,lo

    const int tid  = threadIdx.x;
    const int bid  = blockIdx.x;
    const int cg   = bid & 31;          // n-group
    const int rg   = bid >> 5;          // row-group
    const int n0   = cg * 16;
    const int r0   = rg * 64;
    const int lane = tid & 31;
    const int wid  = tid >> 5;
    const int wr   = (wid & 3) * 16;    // warp row offset
    const int wc   = (wid >> 2) * 32;   // warp col offset
    const int g4r  = lane >> 2;
    const int lk   = lane & 3;
    const int lx2  = lk * 2;

    // ---- load + split Wh slice once: WhHi/WhLo[col][k], col = g*16+j ----
    for (int idx = tid; idx < 512 * 16; idx += 256) {
        int k = idx >> 4, q = idx & 15;
        int g = q >> 2, jj = (q & 3) * 4;
        float4 w = *(const float4*)(Wh + (size_t)k * G4 + g * N_ + n0 + jj);
        int cb = g * 16 + jj;
        __nv_bfloat16 hi, lo;
        bf16_split(w.x, hi, lo); WhHi[(cb + 0) * KS_BF + k] = hi; WhLo[(cb + 0) * KS_BF + k] = lo;
        bf16_split(w.y, hi, lo); WhHi[(cb + 1) * KS_BF + k] = hi; WhLo[(cb + 1) * KS_BF + k] = lo;
        bf16_split(w.z, hi, lo); WhHi[(cb + 2) * KS_BF + k] = hi; WhLo[(cb + 2) * KS_BF + k] = lo;
        bf16_split(w.w, hi, lo); WhHi[(cb + 3) * KS_BF + k] = hi; WhLo[(cb + 3) * KS_BF + k] = lo;
    }

    // ---- cell state in registers ----
    const int prow = tid >> 2;
    const int pj0  = (tid & 3) * 4;
    float4 creg = *(const float4*)(c0 + (size_t)(r0 + prow) * N_ + n0 + pj0);

    __syncthreads();

    // staging mapping for 128-k chunks: row = tid>>2, 4 threads/row,
    // each thread covers 32 floats: [(tid&3)*32 + q*4), q=0..7
    const int srow = tid >> 2;
    const int skq  = tid & 3;
    const int rlo  = r0 + wr + g4r;      // mma row base

    // ---- xz prefetch (t = 0) ----
    float2 xzp[8];
#pragma unroll
    for (int sub = 0; sub < 4; sub++) {
        int c    = wc + sub * 8 + lx2;
        int gate = c >> 4, jj = c & 15;
        size_t base = (size_t)gate * N_ + n0 + jj;
        xzp[sub * 2 + 0] = __ldcg((const float2*)(g_xz + base + (size_t)rlo * G4));
        xzp[sub * 2 + 1] = __ldcg((const float2*)(g_xz + base + (size_t)(rlo + 8) * G4));
    }

    for (int t = 0; t < T_; t++) {
        const float* __restrict__ h_in  = g_h[t & 1];
        float*       __restrict__ h_out = g_h[(t + 1) & 1];

        // ---- acc init from prefetched xz ----
        float acc[4][4];
#pragma unroll
        for (int sub = 0; sub < 4; sub++) {
            acc[sub][0] = xzp[sub * 2 + 0].x; acc[sub][1] = xzp[sub * 2 + 0].y;
            acc[sub][2] = xzp[sub * 2 + 1].x; acc[sub][3] = xzp[sub * 2 + 1].y;
        }

        // ---- GEMM over K=512 in 4 chunks of 128, double-buffered staging ----
        const float* hrow = h_in + (size_t)(r0 + srow) * N_ + skq * 32;
        float4 pf[8];
#pragma unroll
        for (int q = 0; q < 8; q++)
            pf[q] = __ldcg((const float4*)(hrow + q * 4));

        for (int kc = 0; kc < 4; kc++) {
            unsigned* hHiW = (unsigned*)(hBase + (kc & 1) * 2 * HA_BYTES);
            unsigned* hLoW = hHiW + HA_BYTES / 4;

#pragma unroll
            for (int q = 0; q < 8; q++) {
                uint2 hw, lw;
                split4(pf[q], hw, lw);
                int widx = srow * HA_W + skq * 16 + q * 2;
                *(uint2*)(hHiW + widx) = hw;
                *(uint2*)(hLoW + widx) = lw;
            }
            if (kc < 3) {
#pragma unroll
                for (int q = 0; q < 8; q++)
                    pf[q] = __ldcg((const float4*)(hrow + (kc + 1) * 128 + q * 4));
            }
            __syncthreads();

            const int aBase = (wr + g4r) * HA_W + lk;
#pragma unroll
            for (int k16 = 0; k16 < 8; k16++) {
                const int aw = aBase + k16 * 8;
                unsigned aHi[4], aLo[4];
                aHi[0] = hHiW[aw];              aHi[1] = hHiW[aw + 8 * HA_W];
                aHi[2] = hHiW[aw + 4];          aHi[3] = hHiW[aw + 8 * HA_W + 4];
                aLo[0] = hLoW[aw];              aLo[1] = hLoW[aw + 8 * HA_W];
                aLo[2] = hLoW[aw + 4];          aLo[3] = hLoW[aw + 8 * HA_W + 4];
                const int kAbs = kc * 64 + lk + k16 * 8;
#pragma unroll
                for (int sub = 0; sub < 4; sub++) {
                    const int col = wc + sub * 8 + g4r;
                    const int bw  = col * KS_W + kAbs;
                    unsigned bHi[2], bLo[2];
                    bHi[0] = WhHiW[bw]; bHi[1] = WhHiW[bw + 4];
                    bLo[0] = WhLoW[bw]; bLo[1] = WhLoW[bw + 4];
                    mma_bf16(acc[sub], aHi, bHi);
                    mma_bf16(acc[sub], aHi, bLo);
                    mma_bf16(acc[sub], aLo, bHi);
                }
            }
            // no tail sync: next store targets the other buffer; head sync orders it
        }

        // ---- exchange z through SMEM (buf0 region; last compute used buf1) ----
        float* zs = (float*)hBase;
        {
            const int rl = wr + g4r;
#pragma unroll
            for (int sub = 0; sub < 4; sub++) {
                int c = wc + sub * 8 + lx2;
                *(float2*)(zs + (size_t)rl * Z_STRIDE + c)       = make_float2(acc[sub][0], acc[sub][1]);
                *(float2*)(zs + (size_t)(rl + 8) * Z_STRIDE + c) = make_float2(acc[sub][2], acc[sub][3]);
            }
        }
        __syncthreads();

        // ---- pointwise gates + c/h update (fast math) ----
        {
            const float* zr = zs + (size_t)prow * Z_STRIDE + pj0;
            float4 zi = *(const float4*)(zr + 0);
            float4 zf = *(const float4*)(zr + 16);
            float4 zg = *(const float4*)(zr + 32);
            float4 zo = *(const float4*)(zr + 48);

            float4 hv;
            creg.x = sigf(zf.x) * creg.x + sigf(zi.x) * tanhf_fast(zg.x); hv.x = sigf(zo.x) * tanhf_fast(creg.x);
            creg.y = sigf(zf.y) * creg.y + sigf(zi.y) * tanhf_fast(zg.y); hv.y = sigf(zo.y) * tanhf_fast(creg.y);
            creg.z = sigf(zf.z) * creg.z + sigf(zi.z) * tanhf_fast(zg.z); hv.z = sigf(zo.z) * tanhf_fast(creg.z);
            creg.w = sigf(zf.w) * creg.w + sigf(zi.w) * tanhf_fast(zg.w); hv.w = sigf(zo.w) * tanhf_fast(creg.w);

            size_t off = (size_t)(r0 + prow) * N_ + n0 + pj0;
            *(float4*)(h_out + off) = hv;
            *(float4*)(g_hs + (size_t)t * B_ * N_ + off) = hv;
        }

        // ---- prefetch next step's xz (latency hidden under barrier poll) ----
        if (t + 1 < T_) {
#pragma unroll
            for (int sub = 0; sub < 4; sub++) {
                int c    = wc + sub * 8 + lx2;
                int gate = c >> 4, jj = c & 15;
                size_t base = (size_t)(t + 1) * B_ * G4 + (size_t)gate * N_ + n0 + jj;
                xzp[sub * 2 + 0] = __ldcg((const float2*)(g_xz + base + (size_t)rlo * G4));
                xzp[sub * 2 + 1] = __ldcg((const float2*)(g_xz + base + (size_t)(rlo + 8) * G4));
            }
        }

        // ---- full-grid barrier (all 128 blocks resident) ----
        __threadfence();
        __syncthreads();
        if (tid == 0) {
            asm volatile("st.global.release.gpu.u32 [%0], %1;"
                         :: "l"(&g_flags[bid * 32]), "r"((unsigned)(t + 1)) : "memory");
        }
        if (tid < NBLK) {
            unsigned v;
            do {
                asm volatile("ld.global.acquire.gpu.u32 %0, [%1];"
                             : "=r"(v) : "l"(&g_flags[tid * 32]) : "memory");
                if (v >= (unsigned)(t + 1)) break;
                __nanosleep(20);
            } while (true);
        }
        __syncthreads();
    }
}

// ---------------------------------------------------------------------------
// Kernel D (tensor): logits[b][t][v] = bd[v] + sum_n hs[t][b][n] * Wd[n][v]
// ---------------------------------------------------------------------------
__global__ void __launch_bounds__(256)
out_gemm_tc(const float* __restrict__ Wd,
            const float* __restrict__ bd,
            float*       __restrict__ out) {
    unsigned* AhiW = (unsigned*)smem_raw;
    unsigned* AloW = AhiW + PLANE;
    unsigned* BhiW = AloW + PLANE;
    unsigned* BloW = BhiW + PLANE;

    const int tid  = threadIdx.x;
    const int r0   = blockIdx.x * 128;
    const int lane = tid & 31;
    const int wid  = tid >> 5;
    const int wr   = (wid & 3) * 32;
    const int wc   = (wid >> 2) * 64;
    const int g4r  = lane >> 2;
    const int lk   = lane & 3;
    const int lx2  = lk * 2;

    float acc[2][8][4];
#pragma unroll
    for (int f = 0; f < 2; f++)
#pragma unroll
        for (int s = 0; s < 8; s++)
#pragma unroll
            for (int i = 0; i < 4; i++) acc[f][s][i] = 0.f;

    const int srow = tid >> 1;
    const int sqb  = (tid & 1) * 8;
    const int bc   = tid & 127;
    const int bkh  = tid >> 7;

    for (int kc = 0; kc < 8; kc++) {
#pragma unroll
        for (int q = 0; q < 8; q++) {
            float4 v = __ldcg((const float4*)(g_hs + (size_t)(r0 + srow) * N_ + kc * 64 + (sqb + q) * 4));
            uint2 hw, lw;
            split4(v, hw, lw);
            int widx = srow * GW + (sqb + q) * 2;
            *(uint2*)(AhiW + widx) = hw;
            *(uint2*)(AloW + widx) = lw;
        }
#pragma unroll
        for (int kk = 0; kk < 16; kk++) {
            int k0 = kc * 64 + bkh * 32 + kk * 2;
            float a = Wd[(size_t)k0 * V_ + bc];
            float b = Wd[(size_t)(k0 + 1) * V_ + bc];
            __nv_bfloat16 ha, la, hb, lb;
            bf16_split(a, ha, la); bf16_split(b, hb, lb);
            int widx = bc * GW + bkh * 16 + kk;
            BhiW[widx] = pack_bf2(ha, hb);
            BloW[widx] = pack_bf2(la, lb);
        }
        __syncthreads();

        gemm_chunk(AhiW, AloW, BhiW, BloW, wr, wc, g4r, lk, acc);
        __syncthreads();
    }

#pragma unroll
    for (int f = 0; f < 2; f++) {
        int rlo = r0 + wr + f * 16 + g4r;
        int t0 = rlo >> 8,        b0 = rlo & 255;
        int t1 = (rlo + 8) >> 8,  b1 = (rlo + 8) & 255;
        size_t o0 = ((size_t)b0 * T_ + t0) * V_;
        size_t o1 = ((size_t)b1 * T_ + t1) * V_;
#pragma unroll
        for (int sub = 0; sub < 8; sub++) {
            int v = wc + sub * 8 + lx2;
            float2 bb = *(const float2*)(bd + v);
            *(float2*)(out + o0 + v) = make_float2(acc[f][sub][0] + bb.x, acc[f][sub][1] + bb.y);
            *(float2*)(out + o1 + v) = make_float2(acc[f][sub][2] + bb.x, acc[f][sub][3] + bb.y);
        }
    }
}

// ---------------------------------------------------------------------------
extern "C" void kernel_launch(void* const* d_in, const int* in_sizes, int n_in,
                              void* d_out, int out_size) {
    const int*   X    = (const int*)  d_in[0];
    const float* h0   = (const float*)d_in[1];
    const float* c0   = (const float*)d_in[2];
    const float* emb  = (const float*)d_in[3];
    const float* Wx   = (const float*)d_in[4];
    const float* Wh   = (const float*)d_in[5];
    const float* bias = (const float*)d_in[6];
    const float* Wd   = (const float*)d_in[7];
    const float* bd   = (const float*)d_in[8];
    float* out = (float*)d_out;

    cudaFuncSetAttribute(lstm_persistent, cudaFuncAttributeMaxDynamicSharedMemorySize, SMEM_TOTAL_LSTM);
    cudaFuncSetAttribute(input_gemm_tc,  cudaFuncAttributeMaxDynamicSharedMemorySize, SMEM_GEMM);
    cudaFuncSetAttribute(out_gemm_tc,    cudaFuncAttributeMaxDynamicSharedMemorySize, SMEM_GEMM);

    init_kernel<<<(B_ * N_ + 255) / 256, 256>>>(h0);
    input_gemm_tc<<<dim3(G4 / 128, (T_ * B_) / 128), 256, SMEM_GEMM>>>(X, emb, Wx, bias);
    lstm_persistent<<<NBLK, 256, SMEM_TOTAL_LSTM>>>(Wh, c0);
    out_gemm_tc<<<(T_ * B_) / 128, 256, SMEM_GEMM>>>(Wd, bd, out);
}

// round 12
// speedup vs baseline: 1.5176x; 1.5176x over previous
#include <cuda_runtime.h>
#include <cuda_bf16.h>
#include <math.h>

#define B_  256
#define T_  256
#define E_  64
#define N_  512
#define V_  128
#define G4  2048   // 4*N
#define NBLK 128

#define KS_BF 520   // Wh SMEM stride in bf16: [col][k], padded (260 words % 32 == 4)
#define KS_W  260
#define WX_BF 72    // Wx SMEM stride in bf16: [col][k], padded (36 words % 32 == 4)
#define WX_W  36
#define EMB_BF 68   // emb SMEM stride in bf16: [vocab][k] (34 words)
#define EMB_W  34
#define HA_BF 72    // hA staging stride in bf16: [row][k], padded
#define HA_W  36
#define Z_STRIDE 68 // z-exchange float stride

// SMEM byte offsets (recurrence)
#define OFF_WHI   0
#define OFF_WLO   (64 * KS_BF * 2)                // 66560
#define OFF_WXHI  (2 * 64 * KS_BF * 2)            // 133120
#define OFF_WXLO  (OFF_WXHI + 64 * WX_BF * 2)     // 142336
#define OFF_EMBHI (OFF_WXLO + 64 * WX_BF * 2)     // 151552
#define OFF_EMBLO (OFF_EMBHI + 128 * EMB_BF * 2)  // 168960
#define OFF_XIDS  (OFF_EMBLO + 128 * EMB_BF * 2)  // 186368
#define OFF_HA    (OFF_XIDS + 256)                // 186624
#define HA_BYTES  (64 * HA_BF * 2)                // 9216 (per plane; buffer = 2 planes)
#define SMEM_TOTAL_LSTM (OFF_HA + 4 * HA_BYTES)   // 223488

// out GEMM kernel: 4 planes of [128][36 words]
#define GW 36
#define PLANE (128 * GW)
#define SMEM_GEMM (4 * PLANE * 4)                 // 73728 bytes

// ---- scratch (static device memory; no allocations) ----
__device__ float g_hs[(size_t)T_ * B_ * N_];   // [T,B,N] hidden states for final dense
__device__ float g_h[2][B_ * N_];              // ping-pong h
__device__ int   g_xt[T_ * B_];                // X transposed: [t][b]
__device__ unsigned g_flags[NBLK * 32];        // grid barrier flags, 128B-padded

// ---------------------------------------------------------------------------
__device__ __forceinline__ float sigf(float x) {
    return __fdividef(1.f, 1.f + __expf(-x));
}

__device__ __forceinline__ float tanhf_fast(float x) {
    float t = __expf(-2.f * fabsf(x));
    float r = __fdividef(1.f - t, 1.f + t);
    return copysignf(r, x);
}

__device__ __forceinline__ void mma_bf16(float* d, const unsigned* a, const unsigned* b) {
    asm volatile(
        "mma.sync.aligned.m16n8k16.row.col.f32.bf16.bf16.f32 "
        "{%0,%1,%2,%3}, {%4,%5,%6,%7}, {%8,%9}, {%0,%1,%2,%3};"
        : "+f"(d[0]), "+f"(d[1]), "+f"(d[2]), "+f"(d[3])
        : "r"(a[0]), "r"(a[1]), "r"(a[2]), "r"(a[3]), "r"(b[0]), "r"(b[1]));
}

__device__ __forceinline__ void bf16_split(float x, __nv_bfloat16& hi, __nv_bfloat16& lo) {
    hi = __float2bfloat16(x);
    lo = __float2bfloat16(x - __bfloat162float(hi));
}

__device__ __forceinline__ unsigned pack_bf2(__nv_bfloat16 lo, __nv_bfloat16 hi) {
    unsigned short ul = __bfloat16_as_ushort(lo);
    unsigned short uh = __bfloat16_as_ushort(hi);
    return (unsigned)ul | ((unsigned)uh << 16);
}

__device__ __forceinline__ void split4(float4 v, uint2& hw, uint2& lw) {
    __nv_bfloat16 h0, l0, h1, l1, h2, l2, h3, l3;
    bf16_split(v.x, h0, l0); bf16_split(v.y, h1, l1);
    bf16_split(v.z, h2, l2); bf16_split(v.w, h3, l3);
    hw = make_uint2(pack_bf2(h0, h1), pack_bf2(h2, h3));
    lw = make_uint2(pack_bf2(l0, l1), pack_bf2(l2, l3));
}

extern __shared__ char smem_raw[];

// ---------------------------------------------------------------------------
// init: load h_0, transpose X, reset barrier flags
// ---------------------------------------------------------------------------
__global__ void init_kernel(const float* __restrict__ h0, const int* __restrict__ X) {
    int i = blockIdx.x * blockDim.x + threadIdx.x;
    if (i < B_ * N_) g_h[0][i] = h0[i];
    if (i < T_ * B_) {
        int t = i >> 8, b = i & 255;
        g_xt[i] = X[b * T_ + t];
    }
    if (i < NBLK) g_flags[i * 32] = 0u;
}

// ---------------------------------------------------------------------------
// Persistent LSTM with FUSED input projection:
//   per step, chunk 0 = emb-gather @ Wx slice (K=64), chunks 1..8 = h @ Wh.
//   acc starts from bias; no g_xz anywhere. Inner Wh pipeline identical to R9.
// ---------------------------------------------------------------------------
__global__ void __launch_bounds__(256, 1)
lstm_persistent(const float* __restrict__ Wh, const float* __restrict__ c0,
                const float* __restrict__ Wx, const float* __restrict__ emb,
                const float* __restrict__ bias) {
    __nv_bfloat16* WhHi  = (__nv_bfloat16*)(smem_raw + OFF_WHI);
    __nv_bfloat16* WhLo  = (__nv_bfloat16*)(smem_raw + OFF_WLO);
    __nv_bfloat16* WxHi  = (__nv_bfloat16*)(smem_raw + OFF_WXHI);
    __nv_bfloat16* WxLo  = (__nv_bfloat16*)(smem_raw + OFF_WXLO);
    __nv_bfloat16* embHi = (__nv_bfloat16*)(smem_raw + OFF_EMBHI);
    __nv_bfloat16* embLo = (__nv_bfloat16*)(smem_raw + OFF_EMBLO);
    int* xids            = (int*)(smem_raw + OFF_XIDS);
    char* hBase          = smem_raw + OFF_HA;   // buf0: hi,lo ; buf1: hi,lo

    const unsigned* WhHiW  = (const unsigned*)WhHi;
    const unsigned* WhLoW  = (const unsigned*)WhLo;
    const unsigned* WxHiW  = (const unsigned*)WxHi;
    const unsigned* WxLoW  = (const unsigned*)WxLo;
    const unsigned* embHiW = (const unsigned*)embHi;
    const unsigned* embLoW = (const unsigned*)embLo;

    const int tid  = threadIdx.x;
    const int bid  = blockIdx.x;
    const int cg   = bid & 31;          // n-group
    const int rg   = bid >> 5;          // row-group
    const int n0   = cg * 16;
    const int r0   = rg * 64;
    const int lane = tid & 31;
    const int wid  = tid >> 5;
    const int wr   = (wid & 3) * 16;    // warp row offset
    const int wc   = (wid >> 2) * 32;   // warp col offset
    const int g4r  = lane >> 2;
    const int lk   = lane & 3;
    const int lx2  = lk * 2;

    // ---- load + split Wh slice once: [col][k], col = g*16+j ----
    for (int idx = tid; idx < 512 * 16; idx += 256) {
        int k = idx >> 4, q = idx & 15;
        int g = q >> 2, jj = (q & 3) * 4;
        float4 w = *(const float4*)(Wh + (size_t)k * G4 + g * N_ + n0 + jj);
        int cb = g * 16 + jj;
        __nv_bfloat16 hi, lo;
        bf16_split(w.x, hi, lo); WhHi[(cb + 0) * KS_BF + k] = hi; WhLo[(cb + 0) * KS_BF + k] = lo;
        bf16_split(w.y, hi, lo); WhHi[(cb + 1) * KS_BF + k] = hi; WhLo[(cb + 1) * KS_BF + k] = lo;
        bf16_split(w.z, hi, lo); WhHi[(cb + 2) * KS_BF + k] = hi; WhLo[(cb + 2) * KS_BF + k] = lo;
        bf16_split(w.w, hi, lo); WhHi[(cb + 3) * KS_BF + k] = hi; WhLo[(cb + 3) * KS_BF + k] = lo;
    }
    // ---- load + split Wx slice once: [col][k], K=64 ----
    for (int idx = tid; idx < 64 * 16; idx += 256) {
        int k = idx >> 4, q = idx & 15;
        int g = q >> 2, jj = (q & 3) * 4;
        float4 w = *(const float4*)(Wx + (size_t)k * G4 + g * N_ + n0 + jj);
        int cb = g * 16 + jj;
        __nv_bfloat16 hi, lo;
        bf16_split(w.x, hi, lo); WxHi[(cb + 0) * WX_BF + k] = hi; WxLo[(cb + 0) * WX_BF + k] = lo;
        bf16_split(w.y, hi, lo); WxHi[(cb + 1) * WX_BF + k] = hi; WxLo[(cb + 1) * WX_BF + k] = lo;
        bf16_split(w.z, hi, lo); WxHi[(cb + 2) * WX_BF + k] = hi; WxLo[(cb + 2) * WX_BF + k] = lo;
        bf16_split(w.w, hi, lo); WxHi[(cb + 3) * WX_BF + k] = hi; WxLo[(cb + 3) * WX_BF + k] = lo;
    }
    // ---- load + split full emb table once: [v][k] ----
    for (int idx = tid; idx < 128 * 16; idx += 256) {
        int v = idx >> 4, jj = (idx & 15) * 4;
        float4 w = *(const float4*)(emb + (size_t)v * E_ + jj);
        __nv_bfloat16 hi, lo;
        bf16_split(w.x, hi, lo); embHi[v * EMB_BF + jj + 0] = hi; embLo[v * EMB_BF + jj + 0] = lo;
        bf16_split(w.y, hi, lo); embHi[v * EMB_BF + jj + 1] = hi; embLo[v * EMB_BF + jj + 1] = lo;
        bf16_split(w.z, hi, lo); embHi[v * EMB_BF + jj + 2] = hi; embLo[v * EMB_BF + jj + 2] = lo;
        bf16_split(w.w, hi, lo); embHi[v * EMB_BF + jj + 3] = hi; embLo[v * EMB_BF + jj + 3] = lo;
    }
    // ---- xids for t = 0 ----
    if (tid < 64) xids[tid] = g_xt[r0 + tid];

    // ---- bias for this thread's 4 column-pairs (constant over t) ----
    float2 bias2[4];
#pragma unroll
    for (int sub = 0; sub < 4; sub++) {
        int c = wc + sub * 8 + lx2;
        int gate = c >> 4, jj = c & 15;
        bias2[sub] = *(const float2*)(bias + gate * N_ + n0 + jj);
    }

    // ---- cell state in registers ----
    const int prow = tid >> 2;
    const int pj0  = (tid & 3) * 4;
    float4 creg = *(const float4*)(c0 + (size_t)(r0 + prow) * N_ + n0 + pj0);

    __syncthreads();

    const int srow0 = tid >> 4;            // staging rows: +0,16,32,48
    const int skq   = tid & 15;            // k quad (4 bf16 = 2 words)
    const int aBase = (wr + g4r) * HA_W + lk;

    unsigned* hHiW0 = (unsigned*)hBase;
    unsigned* hLoW0 = hHiW0 + HA_BYTES / 4;

    for (int t = 0; t < T_; t++) {
        const float* __restrict__ h_in  = g_h[t & 1];
        float*       __restrict__ h_out = g_h[(t + 1) & 1];

        // ---- acc init = bias ----
        float acc[4][4];
#pragma unroll
        for (int sub = 0; sub < 4; sub++) {
            acc[sub][0] = bias2[sub].x; acc[sub][1] = bias2[sub].y;
            acc[sub][2] = bias2[sub].x; acc[sub][3] = bias2[sub].y;
        }

        // ---- chunk 0: gather-stage emb rows into buf0 (pre-split copy) ----
#pragma unroll
        for (int q = 0; q < 4; q++) {
            int row = srow0 + q * 16;
            int v   = xids[row];
            uint2 hw = *(const uint2*)(embHiW + v * EMB_W + skq * 2);
            uint2 lw = *(const uint2*)(embLoW + v * EMB_W + skq * 2);
            int widx = row * HA_W + skq * 2;
            *(uint2*)(hHiW0 + widx) = hw;
            *(uint2*)(hLoW0 + widx) = lw;
        }
        // prefetch h chunk 0 (for overall chunk 1)
        float4 pf[4];
#pragma unroll
        for (int q = 0; q < 4; q++)
            pf[q] = __ldcg((const float4*)(h_in + (size_t)(r0 + srow0 + q * 16) * N_ + skq * 4));

        __syncthreads();

        // ---- compute chunk 0: gathered emb @ Wx (K=64) ----
#pragma unroll
        for (int k16 = 0; k16 < 4; k16++) {
            const int aw = aBase + k16 * 8;
            unsigned aHi[4], aLo[4];
            aHi[0] = hHiW0[aw];              aHi[1] = hHiW0[aw + 8 * HA_W];
            aHi[2] = hHiW0[aw + 4];          aHi[3] = hHiW0[aw + 8 * HA_W + 4];
            aLo[0] = hLoW0[aw];              aLo[1] = hLoW0[aw + 8 * HA_W];
            aLo[2] = hLoW0[aw + 4];          aLo[3] = hLoW0[aw + 8 * HA_W + 4];
            const int kAbs = lk + k16 * 8;
#pragma unroll
            for (int sub = 0; sub < 4; sub++) {
                const int col = wc + sub * 8 + g4r;
                const int bw  = col * WX_W + kAbs;
                unsigned bHi[2], bLo[2];
                bHi[0] = WxHiW[bw]; bHi[1] = WxHiW[bw + 4];
                bLo[0] = WxLoW[bw]; bLo[1] = WxLoW[bw + 4];
                mma_bf16(acc[sub], aHi, bHi);
                mma_bf16(acc[sub], aHi, bLo);
                mma_bf16(acc[sub], aLo, bHi);
            }
        }

        // ---- chunks 1..8: h @ Wh (R9 pipeline; chunk c stages buf(c&1)) ----
        for (int j = 0; j < 8; j++) {
            const int c = j + 1;
            unsigned* sHiW = (unsigned*)(hBase + (c & 1) * 2 * HA_BYTES);
            unsigned* sLoW = sHiW + HA_BYTES / 4;
#pragma unroll
            for (int q = 0; q < 4; q++) {
                int row = srow0 + q * 16;
                uint2 hw, lw;
                split4(pf[q], hw, lw);
                int widx = row * HA_W + skq * 2;
                *(uint2*)(sHiW + widx) = hw;
                *(uint2*)(sLoW + widx) = lw;
            }
            if (j < 7) {
#pragma unroll
                for (int q = 0; q < 4; q++)
                    pf[q] = __ldcg((const float4*)(h_in + (size_t)(r0 + srow0 + q * 16) * N_ + (j + 1) * 64 + skq * 4));
            }
            __syncthreads();

#pragma unroll
            for (int k16 = 0; k16 < 4; k16++) {
                const int aw = aBase + k16 * 8;
                unsigned aHi[4], aLo[4];
                aHi[0] = sHiW[aw];              aHi[1] = sHiW[aw + 8 * HA_W];
                aHi[2] = sHiW[aw + 4];          aHi[3] = sHiW[aw + 8 * HA_W + 4];
                aLo[0] = sLoW[aw];              aLo[1] = sLoW[aw + 8 * HA_W];
                aLo[2] = sLoW[aw + 4];          aLo[3] = sLoW[aw + 8 * HA_W + 4];
                const int kAbs = j * 32 + lk + k16 * 8;
#pragma unroll
                for (int sub = 0; sub < 4; sub++) {
                    const int col = wc + sub * 8 + g4r;
                    const int bw  = col * KS_W + kAbs;
                    unsigned bHi[2], bLo[2];
                    bHi[0] = WhHiW[bw]; bHi[1] = WhHiW[bw + 4];
                    bLo[0] = WhLoW[bw]; bLo[1] = WhLoW[bw + 4];
                    mma_bf16(acc[sub], aHi, bHi);
                    mma_bf16(acc[sub], aHi, bLo);
                    mma_bf16(acc[sub], aLo, bHi);
                }
            }
            // no tail sync: next stage targets the other buffer
        }

        // ---- exchange z through SMEM: last compute read buf0 -> z in buf1 ----
        float* zs = (float*)(hBase + 2 * HA_BYTES);
        {
            const int rl = wr + g4r;
#pragma unroll
            for (int sub = 0; sub < 4; sub++) {
                int c = wc + sub * 8 + lx2;
                *(float2*)(zs + (size_t)rl * Z_STRIDE + c)       = make_float2(acc[sub][0], acc[sub][1]);
                *(float2*)(zs + (size_t)(rl + 8) * Z_STRIDE + c) = make_float2(acc[sub][2], acc[sub][3]);
            }
        }
        __syncthreads();

        // ---- pointwise gates + c/h update (fast math) ----
        {
            const float* zr = zs + (size_t)prow * Z_STRIDE + pj0;
            float4 zi = *(const float4*)(zr + 0);
            float4 zf = *(const float4*)(zr + 16);
            float4 zg = *(const float4*)(zr + 32);
            float4 zo = *(const float4*)(zr + 48);

            float4 hv;
            creg.x = sigf(zf.x) * creg.x + sigf(zi.x) * tanhf_fast(zg.x); hv.x = sigf(zo.x) * tanhf_fast(creg.x);
            creg.y = sigf(zf.y) * creg.y + sigf(zi.y) * tanhf_fast(zg.y); hv.y = sigf(zo.y) * tanhf_fast(creg.y);
            creg.z = sigf(zf.z) * creg.z + sigf(zi.z) * tanhf_fast(zg.z); hv.z = sigf(zo.z) * tanhf_fast(creg.z);
            creg.w = sigf(zf.w) * creg.w + sigf(zi.w) * tanhf_fast(zg.w); hv.w = sigf(zo.w) * tanhf_fast(creg.w);

            size_t off = (size_t)(r0 + prow) * N_ + n0 + pj0;
            *(float4*)(h_out + off) = hv;
            *(float4*)(g_hs + (size_t)t * B_ * N_ + off) = hv;
        }

        // ---- load next step's xids (read only after the barrier below) ----
        if (t + 1 < T_ && tid < 64)
            xids[tid] = g_xt[(t + 1) * B_ + r0 + tid];

        // ---- full-grid barrier (all 128 blocks resident) ----
        __threadfence();
        __syncthreads();
        if (tid == 0) {
            asm volatile("st.global.release.gpu.u32 [%0], %1;"
                         :: "l"(&g_flags[bid * 32]), "r"((unsigned)(t + 1)) : "memory");
        }
        if (tid < NBLK) {
            unsigned v;
            do {
                asm volatile("ld.global.acquire.gpu.u32 %0, [%1];"
                             : "=r"(v) : "l"(&g_flags[tid * 32]) : "memory");
                if (v >= (unsigned)(t + 1)) break;
                __nanosleep(20);
            } while (true);
        }
        __syncthreads();
    }
}

// ---------------------------------------------------------------------------
// out GEMM core (unchanged from R9)
// ---------------------------------------------------------------------------
__device__ __forceinline__ void gemm_chunk(const unsigned* AhiW, const unsigned* AloW,
                                           const unsigned* BhiW, const unsigned* BloW,
                                           int wr, int wc, int g4r, int lk,
                                           float acc[2][8][4]) {
#pragma unroll
    for (int k16 = 0; k16 < 4; k16++) {
        unsigned aHi[2][4], aLo[2][4];
#pragma unroll
        for (int f = 0; f < 2; f++) {
            int aw = (wr + f * 16 + g4r) * GW + lk + k16 * 8;
            aHi[f][0] = AhiW[aw];          aHi[f][1] = AhiW[aw + 8 * GW];
            aHi[f][2] = AhiW[aw + 4];      aHi[f][3] = AhiW[aw + 8 * GW + 4];
            aLo[f][0] = AloW[aw];          aLo[f][1] = AloW[aw + 8 * GW];
            aLo[f][2] = AloW[aw + 4];      aLo[f][3] = AloW[aw + 8 * GW + 4];
        }
#pragma unroll
        for (int sub = 0; sub < 8; sub++) {
            int col = wc + sub * 8 + g4r;
            int bw  = col * GW + lk + k16 * 8;
            unsigned bHi[2], bLo[2];
            bHi[0] = BhiW[bw]; bHi[1] = BhiW[bw + 4];
            bLo[0] = BloW[bw]; bLo[1] = BloW[bw + 4];
#pragma unroll
            for (int f = 0; f < 2; f++) {
                mma_bf16(acc[f][sub], aHi[f], bHi);
                mma_bf16(acc[f][sub], aHi[f], bLo);
                mma_bf16(acc[f][sub], aLo[f], bHi);
            }
        }
    }
}

__global__ void __launch_bounds__(256)
out_gemm_tc(const float* __restrict__ Wd,
            const float* __restrict__ bd,
            float*       __restrict__ out) {
    unsigned* AhiW = (unsigned*)smem_raw;
    unsigned* AloW = AhiW + PLANE;
    unsigned* BhiW = AloW + PLANE;
    unsigned* BloW = BhiW + PLANE;

    const int tid  = threadIdx.x;
    const int r0   = blockIdx.x * 128;
    const int lane = tid & 31;
    const int wid  = tid >> 5;
    const int wr   = (wid & 3) * 32;
    const int wc   = (wid >> 2) * 64;
    const int g4r  = lane >> 2;
    const int lk   = lane & 3;
    const int lx2  = lk * 2;

    float acc[2][8][4];
#pragma unroll
    for (int f = 0; f < 2; f++)
#pragma unroll
        for (int s = 0; s < 8; s++)
#pragma unroll
            for (int i = 0; i < 4; i++) acc[f][s][i] = 0.f;

    const int srow = tid >> 1;
    const int sqb  = (tid & 1) * 8;
    const int bc   = tid & 127;
    const int bkh  = tid >> 7;

    for (int kc = 0; kc < 8; kc++) {
#pragma unroll
        for (int q = 0; q < 8; q++) {
            float4 v = __ldcg((const float4*)(g_hs + (size_t)(r0 + srow) * N_ + kc * 64 + (sqb + q) * 4));
            uint2 hw, lw;
            split4(v, hw, lw);
            int widx = srow * GW + (sqb + q) * 2;
            *(uint2*)(AhiW + widx) = hw;
            *(uint2*)(AloW + widx) = lw;
        }
#pragma unroll
        for (int kk = 0; kk < 16; kk++) {
            int k0 = kc * 64 + bkh * 32 + kk * 2;
            float a = Wd[(size_t)k0 * V_ + bc];
            float b = Wd[(size_t)(k0 + 1) * V_ + bc];
            __nv_bfloat16 ha, la, hb, lb;
            bf16_split(a, ha, la); bf16_split(b, hb, lb);
            int widx = bc * GW + bkh * 16 + kk;
            BhiW[widx] = pack_bf2(ha, hb);
            BloW[widx] = pack_bf2(la, lb);
        }
        __syncthreads();

        gemm_chunk(AhiW, AloW, BhiW, BloW, wr, wc, g4r, lk, acc);
        __syncthreads();
    }

#pragma unroll
    for (int f = 0; f < 2; f++) {
        int rlo = r0 + wr + f * 16 + g4r;
        int t0 = rlo >> 8,        b0 = rlo & 255;
        int t1 = (rlo + 8) >> 8,  b1 = (rlo + 8) & 255;
        size_t o0 = ((size_t)b0 * T_ + t0) * V_;
        size_t o1 = ((size_t)b1 * T_ + t1) * V_;
#pragma unroll
        for (int sub = 0; sub < 8; sub++) {
            int v = wc + sub * 8 + lx2;
            float2 bb = *(const float2*)(bd + v);
            *(float2*)(out + o0 + v) = make_float2(acc[f][sub][0] + bb.x, acc[f][sub][1] + bb.y);
            *(float2*)(out + o1 + v) = make_float2(acc[f][sub][2] + bb.x, acc[f][sub][3] + bb.y);
        }
    }
}

// ---------------------------------------------------------------------------
extern "C" void kernel_launch(void* const* d_in, const int* in_sizes, int n_in,
                              void* d_out, int out_size) {
    const int*   X    = (const int*)  d_in[0];
    const float* h0   = (const float*)d_in[1];
    const float* c0   = (const float*)d_in[2];
    const float* emb  = (const float*)d_in[3];
    const float* Wx   = (const float*)d_in[4];
    const float* Wh   = (const float*)d_in[5];
    const float* bias = (const float*)d_in[6];
    const float* Wd   = (const float*)d_in[7];
    const float* bd   = (const float*)d_in[8];
    float* out = (float*)d_out;

    cudaFuncSetAttribute(lstm_persistent, cudaFuncAttributeMaxDynamicSharedMemorySize, SMEM_TOTAL_LSTM);
    cudaFuncSetAttribute(out_gemm_tc,    cudaFuncAttributeMaxDynamicSharedMemorySize, SMEM_GEMM);

    init_kernel<<<(B_ * N_ + 255) / 256, 256>>>(h0, X);
    lstm_persistent<<<NBLK, 256, SMEM_TOTAL_LSTM>>>(Wh, c0, Wx, emb, bias);
    out_gemm_tc<<<(T_ * B_) / 128, 256, SMEM_GEMM>>>(Wd, bd, out);
}

// round 13
// speedup vs baseline: 1.6095x; 1.0605x over previous
#include <cuda_runtime.h>
#include <cuda_bf16.h>
#include <math.h>

#define B_  256
#define T_  256
#define E_  64
#define N_  512
#define V_  128
#define G4  2048   // 4*N
#define NBLK 128

#define KS_BF 520   // Wh SMEM stride in bf16: [col][k], padded (260 words % 32 == 4)
#define KS_W  260
#define WX_BF 72    // Wx SMEM stride in bf16: [col][k], padded (36 words % 32 == 4)
#define WX_W  36
#define EMB_BF 68   // emb SMEM stride in bf16: [vocab][k] (34 words)
#define EMB_W  34
#define HA_BF 72    // hA staging stride in bf16: [row][k], padded
#define HA_W  36
#define Z_STRIDE 68 // z-exchange float stride

// SMEM byte offsets (recurrence)
#define OFF_WHI   0
#define OFF_WLO   (64 * KS_BF * 2)                // 66560
#define OFF_WXHI  (2 * 64 * KS_BF * 2)            // 133120
#define OFF_WXLO  (OFF_WXHI + 64 * WX_BF * 2)     // 142336
#define OFF_EMBHI (OFF_WXLO + 64 * WX_BF * 2)     // 151552
#define OFF_EMBLO (OFF_EMBHI + 128 * EMB_BF * 2)  // 168960
#define OFF_XIDS  (OFF_EMBLO + 128 * EMB_BF * 2)  // 186368
#define OFF_HA    (OFF_XIDS + 256)                // 186624
#define HA_BYTES  (64 * HA_BF * 2)                // 9216 (per plane; buffer = 2 planes)
#define SMEM_TOTAL_LSTM (OFF_HA + 4 * HA_BYTES)   // 223488

// out GEMM kernel: 4 planes of [128][36 words]
#define GW 36
#define PLANE (128 * GW)
#define SMEM_GEMM (4 * PLANE * 4)                 // 73728 bytes

// ---- scratch (static device memory; no allocations) ----
__device__ float g_hs[(size_t)T_ * B_ * N_];   // [T,B,N] hidden states for final dense
__device__ float g_h[2][B_ * N_];              // ping-pong h
__device__ int   g_xt[T_ * B_];                // X transposed: [t][b]
__device__ unsigned g_flags[NBLK * 32];        // grid barrier flags, 128B-padded

// ---------------------------------------------------------------------------
__device__ __forceinline__ float sigf(float x) {
    return __fdividef(1.f, 1.f + __expf(-x));
}

__device__ __forceinline__ float tanhf_fast(float x) {
    float t = __expf(-2.f * fabsf(x));
    float r = __fdividef(1.f - t, 1.f + t);
    return copysignf(r, x);
}

__device__ __forceinline__ void mma_bf16(float* d, const unsigned* a, const unsigned* b) {
    asm volatile(
        "mma.sync.aligned.m16n8k16.row.col.f32.bf16.bf16.f32 "
        "{%0,%1,%2,%3}, {%4,%5,%6,%7}, {%8,%9}, {%0,%1,%2,%3};"
        : "+f"(d[0]), "+f"(d[1]), "+f"(d[2]), "+f"(d[3])
        : "r"(a[0]), "r"(a[1]), "r"(a[2]), "r"(a[3]), "r"(b[0]), "r"(b[1]));
}

__device__ __forceinline__ void bf16_split(float x, __nv_bfloat16& hi, __nv_bfloat16& lo) {
    hi = __float2bfloat16(x);
    lo = __float2bfloat16(x - __bfloat162float(hi));
}

__device__ __forceinline__ unsigned pack_bf2(__nv_bfloat16 lo, __nv_bfloat16 hi) {
    unsigned short ul = __bfloat16_as_ushort(lo);
    unsigned short uh = __bfloat16_as_ushort(hi);
    return (unsigned)ul | ((unsigned)uh << 16);
}

__device__ __forceinline__ void split4(float4 v, uint2& hw, uint2& lw) {
    __nv_bfloat16 h0, l0, h1, l1, h2, l2, h3, l3;
    bf16_split(v.x, h0, l0); bf16_split(v.y, h1, l1);
    bf16_split(v.z, h2, l2); bf16_split(v.w, h3, l3);
    hw = make_uint2(pack_bf2(h0, h1), pack_bf2(h2, h3));
    lw = make_uint2(pack_bf2(l0, l1), pack_bf2(l2, l3));
}

extern __shared__ char smem_raw[];

// ---------------------------------------------------------------------------
// init: load h_0, transpose X, reset barrier flags
// ---------------------------------------------------------------------------
__global__ void init_kernel(const float* __restrict__ h0, const int* __restrict__ X) {
    int i = blockIdx.x * blockDim.x + threadIdx.x;
    if (i < B_ * N_) g_h[0][i] = h0[i];
    if (i < T_ * B_) {
        int t = i >> 8, b = i & 255;
        g_xt[i] = X[b * T_ + t];
    }
    if (i < NBLK) g_flags[i * 32] = 0u;
}

// ---------------------------------------------------------------------------
// Persistent LSTM with fused input projection (R12) + cheap barrier:
//   row-group-scoped flags (only the 32 blocks sharing h rows), release-store
//   publication without __threadfence, and no barrier after the last step.
// ---------------------------------------------------------------------------
__global__ void __launch_bounds__(256, 1)
lstm_persistent(const float* __restrict__ Wh, const float* __restrict__ c0,
                const float* __restrict__ Wx, const float* __restrict__ emb,
                const float* __restrict__ bias) {
    __nv_bfloat16* WhHi  = (__nv_bfloat16*)(smem_raw + OFF_WHI);
    __nv_bfloat16* WhLo  = (__nv_bfloat16*)(smem_raw + OFF_WLO);
    __nv_bfloat16* WxHi  = (__nv_bfloat16*)(smem_raw + OFF_WXHI);
    __nv_bfloat16* WxLo  = (__nv_bfloat16*)(smem_raw + OFF_WXLO);
    __nv_bfloat16* embHi = (__nv_bfloat16*)(smem_raw + OFF_EMBHI);
    __nv_bfloat16* embLo = (__nv_bfloat16*)(smem_raw + OFF_EMBLO);
    int* xids            = (int*)(smem_raw + OFF_XIDS);
    char* hBase          = smem_raw + OFF_HA;   // buf0: hi,lo ; buf1: hi,lo

    const unsigned* WhHiW  = (const unsigned*)WhHi;
    const unsigned* WhLoW  = (const unsigned*)WhLo;
    const unsigned* WxHiW  = (const unsigned*)WxHi;
    const unsigned* WxLoW  = (const unsigned*)WxLo;
    const unsigned* embHiW = (const unsigned*)embHi;
    const unsigned* embLoW = (const unsigned*)embLo;

    const int tid  = threadIdx.x;
    const int bid  = blockIdx.x;
    const int cg   = bid & 31;          // n-group
    const int rg   = bid >> 5;          // row-group
    const int n0   = cg * 16;
    const int r0   = rg * 64;
    const int lane = tid & 31;
    const int wid  = tid >> 5;
    const int wr   = (wid & 3) * 16;    // warp row offset
    const int wc   = (wid >> 2) * 32;   // warp col offset
    const int g4r  = lane >> 2;
    const int lk   = lane & 3;
    const int lx2  = lk * 2;

    // ---- load + split Wh slice once: [col][k], col = g*16+j ----
    for (int idx = tid; idx < 512 * 16; idx += 256) {
        int k = idx >> 4, q = idx & 15;
        int g = q >> 2, jj = (q & 3) * 4;
        float4 w = *(const float4*)(Wh + (size_t)k * G4 + g * N_ + n0 + jj);
        int cb = g * 16 + jj;
        __nv_bfloat16 hi, lo;
        bf16_split(w.x, hi, lo); WhHi[(cb + 0) * KS_BF + k] = hi; WhLo[(cb + 0) * KS_BF + k] = lo;
        bf16_split(w.y, hi, lo); WhHi[(cb + 1) * KS_BF + k] = hi; WhLo[(cb + 1) * KS_BF + k] = lo;
        bf16_split(w.z, hi, lo); WhHi[(cb + 2) * KS_BF + k] = hi; WhLo[(cb + 2) * KS_BF + k] = lo;
        bf16_split(w.w, hi, lo); WhHi[(cb + 3) * KS_BF + k] = hi; WhLo[(cb + 3) * KS_BF + k] = lo;
    }
    // ---- load + split Wx slice once: [col][k], K=64 ----
    for (int idx = tid; idx < 64 * 16; idx += 256) {
        int k = idx >> 4, q = idx & 15;
        int g = q >> 2, jj = (q & 3) * 4;
        float4 w = *(const float4*)(Wx + (size_t)k * G4 + g * N_ + n0 + jj);
        int cb = g * 16 + jj;
        __nv_bfloat16 hi, lo;
        bf16_split(w.x, hi, lo); WxHi[(cb + 0) * WX_BF + k] = hi; WxLo[(cb + 0) * WX_BF + k] = lo;
        bf16_split(w.y, hi, lo); WxHi[(cb + 1) * WX_BF + k] = hi; WxLo[(cb + 1) * WX_BF + k] = lo;
        bf16_split(w.z, hi, lo); WxHi[(cb + 2) * WX_BF + k] = hi; WxLo[(cb + 2) * WX_BF + k] = lo;
        bf16_split(w.w, hi, lo); WxHi[(cb + 3) * WX_BF + k] = hi; WxLo[(cb + 3) * WX_BF + k] = lo;
    }
    // ---- load + split full emb table once: [v][k] ----
    for (int idx = tid; idx < 128 * 16; idx += 256) {
        int v = idx >> 4, jj = (idx & 15) * 4;
        float4 w = *(const float4*)(emb + (size_t)v * E_ + jj);
        __nv_bfloat16 hi, lo;
        bf16_split(w.x, hi, lo); embHi[v * EMB_BF + jj + 0] = hi; embLo[v * EMB_BF + jj + 0] = lo;
        bf16_split(w.y, hi, lo); embHi[v * EMB_BF + jj + 1] = hi; embLo[v * EMB_BF + jj + 1] = lo;
        bf16_split(w.z, hi, lo); embHi[v * EMB_BF + jj + 2] = hi; embLo[v * EMB_BF + jj + 2] = lo;
        bf16_split(w.w, hi, lo); embHi[v * EMB_BF + jj + 3] = hi; embLo[v * EMB_BF + jj + 3] = lo;
    }
    // ---- xids for t = 0 ----
    if (tid < 64) xids[tid] = g_xt[r0 + tid];

    // ---- bias for this thread's 4 column-pairs (constant over t) ----
    float2 bias2[4];
#pragma unroll
    for (int sub = 0; sub < 4; sub++) {
        int c = wc + sub * 8 + lx2;
        int gate = c >> 4, jj = c & 15;
        bias2[sub] = *(const float2*)(bias + gate * N_ + n0 + jj);
    }

    // ---- cell state in registers ----
    const int prow = tid >> 2;
    const int pj0  = (tid & 3) * 4;
    float4 creg = *(const float4*)(c0 + (size_t)(r0 + prow) * N_ + n0 + pj0);

    __syncthreads();

    const int srow0 = tid >> 4;            // staging rows: +0,16,32,48
    const int skq   = tid & 15;            // k quad (4 bf16 = 2 words)
    const int aBase = (wr + g4r) * HA_W + lk;

    unsigned* hHiW0 = (unsigned*)hBase;
    unsigned* hLoW0 = hHiW0 + HA_BYTES / 4;

    for (int t = 0; t < T_; t++) {
        const float* __restrict__ h_in  = g_h[t & 1];
        float*       __restrict__ h_out = g_h[(t + 1) & 1];

        // ---- acc init = bias ----
        float acc[4][4];
#pragma unroll
        for (int sub = 0; sub < 4; sub++) {
            acc[sub][0] = bias2[sub].x; acc[sub][1] = bias2[sub].y;
            acc[sub][2] = bias2[sub].x; acc[sub][3] = bias2[sub].y;
        }

        // ---- chunk 0: gather-stage emb rows into buf0 (pre-split copy) ----
#pragma unroll
        for (int q = 0; q < 4; q++) {
            int row = srow0 + q * 16;
            int v   = xids[row];
            uint2 hw = *(const uint2*)(embHiW + v * EMB_W + skq * 2);
            uint2 lw = *(const uint2*)(embLoW + v * EMB_W + skq * 2);
            int widx = row * HA_W + skq * 2;
            *(uint2*)(hHiW0 + widx) = hw;
            *(uint2*)(hLoW0 + widx) = lw;
        }
        // prefetch h chunk 0 (for overall chunk 1)
        float4 pf[4];
#pragma unroll
        for (int q = 0; q < 4; q++)
            pf[q] = __ldcg((const float4*)(h_in + (size_t)(r0 + srow0 + q * 16) * N_ + skq * 4));

        __syncthreads();

        // ---- compute chunk 0: gathered emb @ Wx (K=64) ----
#pragma unroll
        for (int k16 = 0; k16 < 4; k16++) {
            const int aw = aBase + k16 * 8;
            unsigned aHi[4], aLo[4];
            aHi[0] = hHiW0[aw];              aHi[1] = hHiW0[aw + 8 * HA_W];
            aHi[2] = hHiW0[aw + 4];          aHi[3] = hHiW0[aw + 8 * HA_W + 4];
            aLo[0] = hLoW0[aw];              aLo[1] = hLoW0[aw + 8 * HA_W];
            aLo[2] = hLoW0[aw + 4];          aLo[3] = hLoW0[aw + 8 * HA_W + 4];
            const int kAbs = lk + k16 * 8;
#pragma unroll
            for (int sub = 0; sub < 4; sub++) {
                const int col = wc + sub * 8 + g4r;
                const int bw  = col * WX_W + kAbs;
                unsigned bHi[2], bLo[2];
                bHi[0] = WxHiW[bw]; bHi[1] = WxHiW[bw + 4];
                bLo[0] = WxLoW[bw]; bLo[1] = WxLoW[bw + 4];
                mma_bf16(acc[sub], aHi, bHi);
                mma_bf16(acc[sub], aHi, bLo);
                mma_bf16(acc[sub], aLo, bHi);
            }
        }

        // ---- chunks 1..8: h @ Wh (chunk c stages buf(c&1)) ----
        for (int j = 0; j < 8; j++) {
            const int c = j + 1;
            unsigned* sHiW = (unsigned*)(hBase + (c & 1) * 2 * HA_BYTES);
            unsigned* sLoW = sHiW + HA_BYTES / 4;
#pragma unroll
            for (int q = 0; q < 4; q++) {
                int row = srow0 + q * 16;
                uint2 hw, lw;
                split4(pf[q], hw, lw);
                int widx = row * HA_W + skq * 2;
                *(uint2*)(sHiW + widx) = hw;
                *(uint2*)(sLoW + widx) = lw;
            }
            if (j < 7) {
#pragma unroll
                for (int q = 0; q < 4; q++)
                    pf[q] = __ldcg((const float4*)(h_in + (size_t)(r0 + srow0 + q * 16) * N_ + (j + 1) * 64 + skq * 4));
            }
            __syncthreads();

#pragma unroll
            for (int k16 = 0; k16 < 4; k16++) {
                const int aw = aBase + k16 * 8;
                unsigned aHi[4], aLo[4];
                aHi[0] = sHiW[aw];              aHi[1] = sHiW[aw + 8 * HA_W];
                aHi[2] = sHiW[aw + 4];          aHi[3] = sHiW[aw + 8 * HA_W + 4];
                aLo[0] = sLoW[aw];              aLo[1] = sLoW[aw + 8 * HA_W];
                aLo[2] = sLoW[aw + 4];          aLo[3] = sLoW[aw + 8 * HA_W + 4];
                const int kAbs = j * 32 + lk + k16 * 8;
#pragma unroll
                for (int sub = 0; sub < 4; sub++) {
                    const int col = wc + sub * 8 + g4r;
                    const int bw  = col * KS_W + kAbs;
                    unsigned bHi[2], bLo[2];
                    bHi[0] = WhHiW[bw]; bHi[1] = WhHiW[bw + 4];
                    bLo[0] = WhLoW[bw]; bLo[1] = WhLoW[bw + 4];
                    mma_bf16(acc[sub], aHi, bHi);
                    mma_bf16(acc[sub], aHi, bLo);
                    mma_bf16(acc[sub], aLo, bHi);
                }
            }
            // no tail sync: next stage targets the other buffer
        }

        // ---- exchange z through SMEM: last compute read buf0 -> z in buf1 ----
        float* zs = (float*)(hBase + 2 * HA_BYTES);
        {
            const int rl = wr + g4r;
#pragma unroll
            for (int sub = 0; sub < 4; sub++) {
                int c = wc + sub * 8 + lx2;
                *(float2*)(zs + (size_t)rl * Z_STRIDE + c)       = make_float2(acc[sub][0], acc[sub][1]);
                *(float2*)(zs + (size_t)(rl + 8) * Z_STRIDE + c) = make_float2(acc[sub][2], acc[sub][3]);
            }
        }
        __syncthreads();

        // ---- pointwise gates + c/h update (fast math) ----
        {
            const float* zr = zs + (size_t)prow * Z_STRIDE + pj0;
            float4 zi = *(const float4*)(zr + 0);
            float4 zf = *(const float4*)(zr + 16);
            float4 zg = *(const float4*)(zr + 32);
            float4 zo = *(const float4*)(zr + 48);

            float4 hv;
            creg.x = sigf(zf.x) * creg.x + sigf(zi.x) * tanhf_fast(zg.x); hv.x = sigf(zo.x) * tanhf_fast(creg.x);
            creg.y = sigf(zf.y) * creg.y + sigf(zi.y) * tanhf_fast(zg.y); hv.y = sigf(zo.y) * tanhf_fast(creg.y);
            creg.z = sigf(zf.z) * creg.z + sigf(zi.z) * tanhf_fast(zg.z); hv.z = sigf(zo.z) * tanhf_fast(creg.z);
            creg.w = sigf(zf.w) * creg.w + sigf(zi.w) * tanhf_fast(zg.w); hv.w = sigf(zo.w) * tanhf_fast(creg.w);

            size_t off = (size_t)(r0 + prow) * N_ + n0 + pj0;
            *(float4*)(h_out + off) = hv;
            *(float4*)(g_hs + (size_t)t * B_ * N_ + off) = hv;
        }

        if (t + 1 < T_) {
            // ---- load next step's xids (consumed after the barrier) ----
            if (tid < 64)
                xids[tid] = g_xt[(t + 1) * B_ + r0 + tid];

            // ---- row-group barrier: only the 32 blocks sharing h rows ----
            // syncthreads orders all threads' h_out stores before tid0's
            // release-store, which publishes them to the acquiring pollers.
            __syncthreads();
            if (tid == 0) {
                asm volatile("st.global.release.gpu.u32 [%0], %1;"
                             :: "l"(&g_flags[bid * 32]), "r"((unsigned)(t + 1)) : "memory");
            }
            if (tid < 32) {
                unsigned v;
                do {
                    asm volatile("ld.global.acquire.gpu.u32 %0, [%1];"
                                 : "=r"(v) : "l"(&g_flags[(rg * 32 + tid) * 32]) : "memory");
                    if (v >= (unsigned)(t + 1)) break;
                    __nanosleep(20);
                } while (true);
            }
            __syncthreads();
        }
    }
}

// ---------------------------------------------------------------------------
// out GEMM core (unchanged from R9)
// ---------------------------------------------------------------------------
__device__ __forceinline__ void gemm_chunk(const unsigned* AhiW, const unsigned* AloW,
                                           const unsigned* BhiW, const unsigned* BloW,
                                           int wr, int wc, int g4r, int lk,
                                           float acc[2][8][4]) {
#pragma unroll
    for (int k16 = 0; k16 < 4; k16++) {
        unsigned aHi[2][4], aLo[2][4];
#pragma unroll
        for (int f = 0; f < 2; f++) {
            int aw = (wr + f * 16 + g4r) * GW + lk + k16 * 8;
            aHi[f][0] = AhiW[aw];          aHi[f][1] = AhiW[aw + 8 * GW];
            aHi[f][2] = AhiW[aw + 4];      aHi[f][3] = AhiW[aw + 8 * GW + 4];
            aLo[f][0] = AloW[aw];          aLo[f][1] = AloW[aw + 8 * GW];
            aLo[f][2] = AloW[aw + 4];      aLo[f][3] = AloW[aw + 8 * GW + 4];
        }
#pragma unroll
        for (int sub = 0; sub < 8; sub++) {
            int col = wc + sub * 8 + g4r;
            int bw  = col * GW + lk + k16 * 8;
            unsigned bHi[2], bLo[2];
            bHi[0] = BhiW[bw]; bHi[1] = BhiW[bw + 4];
            bLo[0] = BloW[bw]; bLo[1] = BloW[bw + 4];
#pragma unroll
            for (int f = 0; f < 2; f++) {
                mma_bf16(acc[f][sub], aHi[f], bHi);
                mma_bf16(acc[f][sub], aHi[f], bLo);
                mma_bf16(acc[f][sub], aLo[f], bHi);
            }
        }
    }
}

__global__ void __launch_bounds__(256)
out_gemm_tc(const float* __restrict__ Wd,
            const float* __restrict__ bd,
            float*       __restrict__ out) {
    unsigned* AhiW = (unsigned*)smem_raw;
    unsigned* AloW = AhiW + PLANE;
    unsigned* BhiW = AloW + PLANE;
    unsigned* BloW = BhiW + PLANE;

    const int tid  = threadIdx.x;
    const int r0   = blockIdx.x * 128;
    const int lane = tid & 31;
    const int wid  = tid >> 5;
    const int wr   = (wid & 3) * 32;
    const int wc   = (wid >> 2) * 64;
    const int g4r  = lane >> 2;
    const int lk   = lane & 3;
    const int lx2  = lk * 2;

    float acc[2][8][4];
#pragma unroll
    for (int f = 0; f < 2; f++)
#pragma unroll
        for (int s = 0; s < 8; s++)
#pragma unroll
            for (int i = 0; i < 4; i++) acc[f][s][i] = 0.f;

    const int srow = tid >> 1;
    const int sqb  = (tid & 1) * 8;
    const int bc   = tid & 127;
    const int bkh  = tid >> 7;

    for (int kc = 0; kc < 8; kc++) {
#pragma unroll
        for (int q = 0; q < 8; q++) {
            float4 v = __ldcg((const float4*)(g_hs + (size_t)(r0 + srow) * N_ + kc * 64 + (sqb + q) * 4));
            uint2 hw, lw;
            split4(v, hw, lw);
            int widx = srow * GW + (sqb + q) * 2;
            *(uint2*)(AhiW + widx) = hw;
            *(uint2*)(AloW + widx) = lw;
        }
#pragma unroll
        for (int kk = 0; kk < 16; kk++) {
            int k0 = kc * 64 + bkh * 32 + kk * 2;
            float a = Wd[(size_t)k0 * V_ + bc];
            float b = Wd[(size_t)(k0 + 1) * V_ + bc];
            __nv_bfloat16 ha, la, hb, lb;
            bf16_split(a, ha, la); bf16_split(b, hb, lb);
            int widx = bc * GW + bkh * 16 + kk;
            BhiW[widx] = pack_bf2(ha, hb);
            BloW[widx] = pack_bf2(la, lb);
        }
        __syncthreads();

        gemm_chunk(AhiW, AloW, BhiW, BloW, wr, wc, g4r, lk, acc);
        __syncthreads();
    }

#pragma unroll
    for (int f = 0; f < 2; f++) {
        int rlo = r0 + wr + f * 16 + g4r;
        int t0 = rlo >> 8,        b0 = rlo & 255;
        int t1 = (rlo + 8) >> 8,  b1 = (rlo + 8) & 255;
        size_t o0 = ((size_t)b0 * T_ + t0) * V_;
        size_t o1 = ((size_t)b1 * T_ + t1) * V_;
#pragma unroll
        for (int sub = 0; sub < 8; sub++) {
            int v = wc + sub * 8 + lx2;
            float2 bb = *(const float2*)(bd + v);
            *(float2*)(out + o0 + v) = make_float2(acc[f][sub][0] + bb.x, acc[f][sub][1] + bb.y);
            *(float2*)(out + o1 + v) = make_float2(acc[f][sub][2] + bb.x, acc[f][sub][3] + bb.y);
        }
    }
}

// ---------------------------------------------------------------------------
extern "C" void kernel_launch(void* const* d_in, const int* in_sizes, int n_in,
                              void* d_out, int out_size) {
    const int*   X    = (const int*)  d_in[0];
    const float* h0   = (const float*)d_in[1];
    const float* c0   = (const float*)d_in[2];
    const float* emb  = (const float*)d_in[3];
    const float* Wx   = (const float*)d_in[4];
    const float* Wh   = (const float*)d_in[5];
    const float* bias = (const float*)d_in[6];
    const float* Wd   = (const float*)d_in[7];
    const float* bd   = (const float*)d_in[8];
    float* out = (float*)d_out;

    cudaFuncSetAttribute(lstm_persistent, cudaFuncAttributeMaxDynamicSharedMemorySize, SMEM_TOTAL_LSTM);
    cudaFuncSetAttribute(out_gemm_tc,    cudaFuncAttributeMaxDynamicSharedMemorySize, SMEM_GEMM);

    init_kernel<<<(B_ * N_ + 255) / 256, 256>>>(h0, X);
    lstm_persistent<<<NBLK, 256, SMEM_TOTAL_LSTM>>>(Wh, c0, Wx, emb, bias);
    out_gemm_tc<<<(T_ * B_) / 128, 256, SMEM_GEMM>>>(Wd, bd, out);
}

// round 14
// speedup vs baseline: 1.6309x; 1.0134x over previous
#include <cuda_runtime.h>
#include <cuda_bf16.h>
#include <math.h>

#define B_  256
#define T_  256
#define E_  64
#define N_  512
#define V_  128
#define G4  2048   // 4*N
#define NBLK 128

#define KS_BF 520   // Wh SMEM stride in bf16: [col][k], padded (260 words % 32 == 4)
#define KS_W  260
#define HA_BF 72    // hA staging stride in bf16: [row][k], padded
#define HA_W  36
#define XZT_W 68    // xzTab stride in floats
#define Z_STRIDE 68 // z-exchange float stride

// SMEM byte offsets (recurrence)
#define OFF_WHI   0
#define OFF_WLO   (64 * KS_BF * 2)                // 66560
#define OFF_XZT   (2 * 64 * KS_BF * 2)            // 133120
#define OFF_XIDS  (OFF_XZT + 128 * XZT_W * 4)     // 167936
#define OFF_HA    (OFF_XIDS + 256)                // 168192
#define HA_BYTES  (64 * HA_BF * 2)                // 9216 (per plane; buffer = 2 planes)
#define SMEM_TOTAL_LSTM (OFF_HA + 4 * HA_BYTES)   // 205056

// out GEMM kernel: 4 planes of [128][36 words]
#define GW 36
#define PLANE (128 * GW)
#define SMEM_GEMM (4 * PLANE * 4)                 // 73728 bytes

// ---- scratch (static device memory; no allocations) ----
__device__ float g_hs[(size_t)T_ * B_ * N_];   // [T,B,N] hidden states for final dense
__device__ float g_h[2][B_ * N_];              // ping-pong h
__device__ int   g_xt[T_ * B_];                // X transposed: [t][b]
__device__ unsigned g_flags[NBLK * 32];        // grid barrier flags, 128B-padded

// ---------------------------------------------------------------------------
__device__ __forceinline__ float sigf(float x) {
    return __fdividef(1.f, 1.f + __expf(-x));
}

__device__ __forceinline__ float tanhf_fast(float x) {
    float t = __expf(-2.f * fabsf(x));
    float r = __fdividef(1.f - t, 1.f + t);
    return copysignf(r, x);
}

__device__ __forceinline__ void mma_bf16(float* d, const unsigned* a, const unsigned* b) {
    asm volatile(
        "mma.sync.aligned.m16n8k16.row.col.f32.bf16.bf16.f32 "
        "{%0,%1,%2,%3}, {%4,%5,%6,%7}, {%8,%9}, {%0,%1,%2,%3};"
        : "+f"(d[0]), "+f"(d[1]), "+f"(d[2]), "+f"(d[3])
        : "r"(a[0]), "r"(a[1]), "r"(a[2]), "r"(a[3]), "r"(b[0]), "r"(b[1]));
}

__device__ __forceinline__ void bf16_split(float x, __nv_bfloat16& hi, __nv_bfloat16& lo) {
    hi = __float2bfloat16(x);
    lo = __float2bfloat16(x - __bfloat162float(hi));
}

__device__ __forceinline__ unsigned pack_bf2(__nv_bfloat16 lo, __nv_bfloat16 hi) {
    unsigned short ul = __bfloat16_as_ushort(lo);
    unsigned short uh = __bfloat16_as_ushort(hi);
    return (unsigned)ul | ((unsigned)uh << 16);
}

__device__ __forceinline__ void split4(float4 v, uint2& hw, uint2& lw) {
    __nv_bfloat16 h0, l0, h1, l1, h2, l2, h3, l3;
    bf16_split(v.x, h0, l0); bf16_split(v.y, h1, l1);
    bf16_split(v.z, h2, l2); bf16_split(v.w, h3, l3);
    hw = make_uint2(pack_bf2(h0, h1), pack_bf2(h2, h3));
    lw = make_uint2(pack_bf2(l0, l1), pack_bf2(l2, l3));
}

extern __shared__ char smem_raw[];

// ---------------------------------------------------------------------------
// init: load h_0, transpose X, reset barrier flags
// ---------------------------------------------------------------------------
__global__ void init_kernel(const float* __restrict__ h0, const int* __restrict__ X) {
    int i = blockIdx.x * blockDim.x + threadIdx.x;
    if (i < B_ * N_) g_h[0][i] = h0[i];
    if (i < T_ * B_) {
        int t = i >> 8, b = i & 255;
        g_xt[i] = X[b * T_ + t];
    }
    if (i < NBLK) g_flags[i * 32] = 0u;
}

// ---------------------------------------------------------------------------
// Persistent LSTM with table-based input projection:
//   xzTab[v][c] = bias + emb[v] @ Wx[:,block col c], precomputed once in fp32.
//   Per step: acc init = table gather by xids; then 8 h@Wh chunks (R13 pipeline);
//   row-group-scoped flag barrier.
// ---------------------------------------------------------------------------
__global__ void __launch_bounds__(256, 1)
lstm_persistent(const float* __restrict__ Wh, const float* __restrict__ c0,
                const float* __restrict__ Wx, const float* __restrict__ emb,
                const float* __restrict__ bias) {
    __nv_bfloat16* WhHi = (__nv_bfloat16*)(smem_raw + OFF_WHI);
    __nv_bfloat16* WhLo = (__nv_bfloat16*)(smem_raw + OFF_WLO);
    float* xzTab        = (float*)(smem_raw + OFF_XZT);
    int* xids           = (int*)(smem_raw + OFF_XIDS);
    char* hBase         = smem_raw + OFF_HA;   // buf0: hi,lo ; buf1: hi,lo

    const unsigned* WhHiW = (const unsigned*)WhHi;
    const unsigned* WhLoW = (const unsigned*)WhLo;

    const int tid  = threadIdx.x;
    const int bid  = blockIdx.x;
    const int cg   = bid & 31;          // n-group
    const int rg   = bid >> 5;          // row-group
    const int n0   = cg * 16;
    const int r0   = rg * 64;
    const int lane = tid & 31;
    const int wid  = tid >> 5;
    const int wr   = (wid & 3) * 16;    // warp row offset
    const int wc   = (wid >> 2) * 32;   // warp col offset
    const int g4r  = lane >> 2;
    const int lk   = lane & 3;
    const int lx2  = lk * 2;

    // ---- load + split Wh slice once: [col][k], col = g*16+j ----
    for (int idx = tid; idx < 512 * 16; idx += 256) {
        int k = idx >> 4, q = idx & 15;
        int g = q >> 2, jj = (q & 3) * 4;
        float4 w = *(const float4*)(Wh + (size_t)k * G4 + g * N_ + n0 + jj);
        int cb = g * 16 + jj;
        __nv_bfloat16 hi, lo;
        bf16_split(w.x, hi, lo); WhHi[(cb + 0) * KS_BF + k] = hi; WhLo[(cb + 0) * KS_BF + k] = lo;
        bf16_split(w.y, hi, lo); WhHi[(cb + 1) * KS_BF + k] = hi; WhLo[(cb + 1) * KS_BF + k] = lo;
        bf16_split(w.z, hi, lo); WhHi[(cb + 2) * KS_BF + k] = hi; WhLo[(cb + 2) * KS_BF + k] = lo;
        bf16_split(w.w, hi, lo); WhHi[(cb + 3) * KS_BF + k] = hi; WhLo[(cb + 3) * KS_BF + k] = lo;
    }

    // ---- precompute xzTab (fp32): stage emb fp32 in hA scratch ----
    {
        float* embF = (float*)hBase;   // [128][64] fp32, 32KB (hA region is 36KB)
        for (int idx = tid; idx < 128 * 16; idx += 256) {
            int v = idx >> 4, jj = (idx & 15) * 4;
            *(float4*)(embF + v * 64 + jj) = *(const float4*)(emb + (size_t)v * E_ + jj);
        }
        __syncthreads();

        const int c     = tid & 63;                       // block-local col 0..63
        const int gcol  = (c >> 4) * N_ + n0 + (c & 15);  // global Wx col
        const int vBase = (tid >> 6) * 32;                // vocab group of 32

        float a[32];
        float bv = bias[gcol];
#pragma unroll
        for (int v = 0; v < 32; v++) a[v] = bv;
        for (int e = 0; e < E_; e++) {
            float wx = Wx[(size_t)e * G4 + gcol];
#pragma unroll
            for (int v = 0; v < 32; v++)
                a[v] = fmaf(embF[(vBase + v) * 64 + e], wx, a[v]);
        }
        __syncthreads();   // embF reads done before xzTab writes... (separate regions, but cheap)
#pragma unroll
        for (int v = 0; v < 32; v++)
            xzTab[(vBase + v) * XZT_W + c] = a[v];
    }

    // ---- xids for t = 0 ----
    if (tid < 64) xids[tid] = g_xt[r0 + tid];

    // ---- cell state in registers ----
    const int prow = tid >> 2;
    const int pj0  = (tid & 3) * 4;
    float4 creg = *(const float4*)(c0 + (size_t)(r0 + prow) * N_ + n0 + pj0);

    __syncthreads();

    const int srow0 = tid >> 4;            // staging rows: +0,16,32,48
    const int skq   = tid & 15;            // k quad (4 bf16 = 2 words)
    const int aBase = (wr + g4r) * HA_W + lk;
    const int arow0 = wr + g4r;            // local mma rows arow0, arow0+8

    for (int t = 0; t < T_; t++) {
        const float* __restrict__ h_in  = g_h[t & 1];
        float*       __restrict__ h_out = g_h[(t + 1) & 1];

        // ---- acc init: gather xz from table by vocab id ----
        float acc[4][4];
        {
            const float* row0 = xzTab + xids[arow0] * XZT_W;
            const float* row1 = xzTab + xids[arow0 + 8] * XZT_W;
#pragma unroll
            for (int sub = 0; sub < 4; sub++) {
                int c = wc + sub * 8 + lx2;
                float2 xlo = *(const float2*)(row0 + c);
                float2 xhi = *(const float2*)(row1 + c);
                acc[sub][0] = xlo.x; acc[sub][1] = xlo.y;
                acc[sub][2] = xhi.x; acc[sub][3] = xhi.y;
            }
        }

        // ---- GEMM over K=512 in 8 chunks of 64, double-buffered staging ----
        float4 pf[4];
#pragma unroll
        for (int q = 0; q < 4; q++)
            pf[q] = __ldcg((const float4*)(h_in + (size_t)(r0 + srow0 + q * 16) * N_ + skq * 4));

        for (int j = 0; j < 8; j++) {
            unsigned* sHiW = (unsigned*)(hBase + (j & 1) * 2 * HA_BYTES);
            unsigned* sLoW = sHiW + HA_BYTES / 4;
#pragma unroll
            for (int q = 0; q < 4; q++) {
                int row = srow0 + q * 16;
                uint2 hw, lw;
                split4(pf[q], hw, lw);
                int widx = row * HA_W + skq * 2;
                *(uint2*)(sHiW + widx) = hw;
                *(uint2*)(sLoW + widx) = lw;
            }
            if (j < 7) {
#pragma unroll
                for (int q = 0; q < 4; q++)
                    pf[q] = __ldcg((const float4*)(h_in + (size_t)(r0 + srow0 + q * 16) * N_ + (j + 1) * 64 + skq * 4));
            }
            __syncthreads();

#pragma unroll
            for (int k16 = 0; k16 < 4; k16++) {
                const int aw = aBase + k16 * 8;
                unsigned aHi[4], aLo[4];
                aHi[0] = sHiW[aw];              aHi[1] = sHiW[aw + 8 * HA_W];
                aHi[2] = sHiW[aw + 4];          aHi[3] = sHiW[aw + 8 * HA_W + 4];
                aLo[0] = sLoW[aw];              aLo[1] = sLoW[aw + 8 * HA_W];
                aLo[2] = sLoW[aw + 4];          aLo[3] = sLoW[aw + 8 * HA_W + 4];
                const int kAbs = j * 32 + lk + k16 * 8;
#pragma unroll
                for (int sub = 0; sub < 4; sub++) {
                    const int col = wc + sub * 8 + g4r;
                    const int bw  = col * KS_W + kAbs;
                    unsigned bHi[2], bLo[2];
                    bHi[0] = WhHiW[bw]; bHi[1] = WhHiW[bw + 4];
                    bLo[0] = WhLoW[bw]; bLo[1] = WhLoW[bw + 4];
                    mma_bf16(acc[sub], aHi, bHi);
                    mma_bf16(acc[sub], aHi, bLo);
                    mma_bf16(acc[sub], aLo, bHi);
                }
            }
            // no tail sync: next stage targets the other buffer
        }

        // ---- exchange z through SMEM: last compute read buf1 -> z in buf0 ----
        float* zs = (float*)hBase;
        {
            const int rl = wr + g4r;
#pragma unroll
            for (int sub = 0; sub < 4; sub++) {
                int c = wc + sub * 8 + lx2;
                *(float2*)(zs + (size_t)rl * Z_STRIDE + c)       = make_float2(acc[sub][0], acc[sub][1]);
                *(float2*)(zs + (size_t)(rl + 8) * Z_STRIDE + c) = make_float2(acc[sub][2], acc[sub][3]);
            }
        }
        __syncthreads();

        // ---- pointwise gates + c/h update (fast math) ----
        {
            const float* zr = zs + (size_t)prow * Z_STRIDE + pj0;
            float4 zi = *(const float4*)(zr + 0);
            float4 zf = *(const float4*)(zr + 16);
            float4 zg = *(const float4*)(zr + 32);
            float4 zo = *(const float4*)(zr + 48);

            float4 hv;
            creg.x = sigf(zf.x) * creg.x + sigf(zi.x) * tanhf_fast(zg.x); hv.x = sigf(zo.x) * tanhf_fast(creg.x);
            creg.y = sigf(zf.y) * creg.y + sigf(zi.y) * tanhf_fast(zg.y); hv.y = sigf(zo.y) * tanhf_fast(creg.y);
            creg.z = sigf(zf.z) * creg.z + sigf(zi.z) * tanhf_fast(zg.z); hv.z = sigf(zo.z) * tanhf_fast(creg.z);
            creg.w = sigf(zf.w) * creg.w + sigf(zi.w) * tanhf_fast(zg.w); hv.w = sigf(zo.w) * tanhf_fast(creg.w);

            size_t off = (size_t)(r0 + prow) * N_ + n0 + pj0;
            *(float4*)(h_out + off) = hv;
            *(float4*)(g_hs + (size_t)t * B_ * N_ + off) = hv;
        }

        if (t + 1 < T_) {
            // ---- load next step's xids (consumed after the barrier) ----
            if (tid < 64)
                xids[tid] = g_xt[(t + 1) * B_ + r0 + tid];

            // ---- row-group barrier: only the 32 blocks sharing h rows ----
            __syncthreads();
            if (tid == 0) {
                asm volatile("st.global.release.gpu.u32 [%0], %1;"
                             :: "l"(&g_flags[bid * 32]), "r"((unsigned)(t + 1)) : "memory");
            }
            if (tid < 32) {
                unsigned v;
                do {
                    asm volatile("ld.global.acquire.gpu.u32 %0, [%1];"
                                 : "=r"(v) : "l"(&g_flags[(rg * 32 + tid) * 32]) : "memory");
                    if (v >= (unsigned)(t + 1)) break;
                    __nanosleep(20);
                } while (true);
            }
            __syncthreads();
        }
    }
}

// ---------------------------------------------------------------------------
// out GEMM core (unchanged)
// ---------------------------------------------------------------------------
__device__ __forceinline__ void gemm_chunk(const unsigned* AhiW, const unsigned* AloW,
                                           const unsigned* BhiW, const unsigned* BloW,
                                           int wr, int wc, int g4r, int lk,
                                           float acc[2][8][4]) {
#pragma unroll
    for (int k16 = 0; k16 < 4; k16++) {
        unsigned aHi[2][4], aLo[2][4];
#pragma unroll
        for (int f = 0; f < 2; f++) {
            int aw = (wr + f * 16 + g4r) * GW + lk + k16 * 8;
            aHi[f][0] = AhiW[aw];          aHi[f][1] = AhiW[aw + 8 * GW];
            aHi[f][2] = AhiW[aw + 4];      aHi[f][3] = AhiW[aw + 8 * GW + 4];
            aLo[f][0] = AloW[aw];          aLo[f][1] = AloW[aw + 8 * GW];
            aLo[f][2] = AloW[aw + 4];      aLo[f][3] = AloW[aw + 8 * GW + 4];
        }
#pragma unroll
        for (int sub = 0; sub < 8; sub++) {
            int col = wc + sub * 8 + g4r;
            int bw  = col * GW + lk + k16 * 8;
            unsigned bHi[2], bLo[2];
            bHi[0] = BhiW[bw]; bHi[1] = BhiW[bw + 4];
            bLo[0] = BloW[bw]; bLo[1] = BloW[bw + 4];
#pragma unroll
            for (int f = 0; f < 2; f++) {
                mma_bf16(acc[f][sub], aHi[f], bHi);
                mma_bf16(acc[f][sub], aHi[f], bLo);
                mma_bf16(acc[f][sub], aLo[f], bHi);
            }
        }
    }
}

__global__ void __launch_bounds__(256)
out_gemm_tc(const float* __restrict__ Wd,
            const float* __restrict__ bd,
            float*       __restrict__ out) {
    unsigned* AhiW = (unsigned*)smem_raw;
    unsigned* AloW = AhiW + PLANE;
    unsigned* BhiW = AloW + PLANE;
    unsigned* BloW = BhiW + PLANE;

    const int tid  = threadIdx.x;
    const int r0   = blockIdx.x * 128;
    const int lane = tid & 31;
    const int wid  = tid >> 5;
    const int wr   = (wid & 3) * 32;
    const int wc   = (wid >> 2) * 64;
    const int g4r  = lane >> 2;
    const int lk   = lane & 3;
    const int lx2  = lk * 2;

    float acc[2][8][4];
#pragma unroll
    for (int f = 0; f < 2; f++)
#pragma unroll
        for (int s = 0; s < 8; s++)
#pragma unroll
            for (int i = 0; i < 4; i++) acc[f][s][i] = 0.f;

    const int srow = tid >> 1;
    const int sqb  = (tid & 1) * 8;
    const int bc   = tid & 127;
    const int bkh  = tid >> 7;

    for (int kc = 0; kc < 8; kc++) {
#pragma unroll
        for (int q = 0; q < 8; q++) {
            float4 v = __ldcg((const float4*)(g_hs + (size_t)(r0 + srow) * N_ + kc * 64 + (sqb + q) * 4));
            uint2 hw, lw;
            split4(v, hw, lw);
            int widx = srow * GW + (sqb + q) * 2;
            *(uint2*)(AhiW + widx) = hw;
            *(uint2*)(AloW + widx) = lw;
        }
#pragma unroll
        for (int kk = 0; kk < 16; kk++) {
            int k0 = kc * 64 + bkh * 32 + kk * 2;
            float a = Wd[(size_t)k0 * V_ + bc];
            float b = Wd[(size_t)(k0 + 1) * V_ + bc];
            __nv_bfloat16 ha, la, hb, lb;
            bf16_split(a, ha, la); bf16_split(b, hb, lb);
            int widx = bc * GW + bkh * 16 + kk;
            BhiW[widx] = pack_bf2(ha, hb);
            BloW[widx] = pack_bf2(la, lb);
        }
        __syncthreads();

        gemm_chunk(AhiW, AloW, BhiW, BloW, wr, wc, g4r, lk, acc);
        __syncthreads();
    }

#pragma unroll
    for (int f = 0; f < 2; f++) {
        int rlo = r0 + wr + f * 16 + g4r;
        int t0 = rlo >> 8,        b0 = rlo & 255;
        int t1 = (rlo + 8) >> 8,  b1 = (rlo + 8) & 255;
        size_t o0 = ((size_t)b0 * T_ + t0) * V_;
        size_t o1 = ((size_t)b1 * T_ + t1) * V_;
#pragma unroll
        for (int sub = 0; sub < 8; sub++) {
            int v = wc + sub * 8 + lx2;
            float2 bb = *(const float2*)(bd + v);
            *(float2*)(out + o0 + v) = make_float2(acc[f][sub][0] + bb.x, acc[f][sub][1] + bb.y);
            *(float2*)(out + o1 + v) = make_float2(acc[f][sub][2] + bb.x, acc[f][sub][3] + bb.y);
        }
    }
}

// ---------------------------------------------------------------------------
extern "C" void kernel_launch(void* const* d_in, const int* in_sizes, int n_in,
                              void* d_out, int out_size) {
    const int*   X    = (const int*)  d_in[0];
    const float* h0   = (const float*)d_in[1];
    const float* c0   = (const float*)d_in[2];
    const float* emb  = (const float*)d_in[3];
    const float* Wx   = (const float*)d_in[4];
    const float* Wh   = (const float*)d_in[5];
    const float* bias = (const float*)d_in[6];
    const float* Wd   = (const float*)d_in[7];
    const float* bd   = (const float*)d_in[8];
    float* out = (float*)d_out;

    cudaFuncSetAttribute(lstm_persistent, cudaFuncAttributeMaxDynamicSharedMemorySize, SMEM_TOTAL_LSTM);
    cudaFuncSetAttribute(out_gemm_tc,    cudaFuncAttributeMaxDynamicSharedMemorySize, SMEM_GEMM);

    init_kernel<<<(B_ * N_ + 255) / 256, 256>>>(h0, X);
    lstm_persistent<<<NBLK, 256, SMEM_TOTAL_LSTM>>>(Wh, c0, Wx, emb, bias);
    out_gemm_tc<<<(T_ * B_) / 128, 256, SMEM_GEMM>>>(Wd, bd, out);
}

// round 15
// speedup vs baseline: 1.6853x; 1.0333x over previous
#include <cuda_runtime.h>
#include <cuda_bf16.h>
#include <math.h>

#define B_  256
#define T_  256
#define E_  64
#define N_  512
#define V_  128
#define G4  2048   // 4*N
#define NBLK 128   // recurrence blocks
#define NWRK 20    // logits worker blocks
#define NTILES 512 // out tiles of 128 rows

#define KS_BF 520   // Wh SMEM stride in bf16: [col][k], padded (260 words % 32 == 4)
#define KS_W  260
#define HA_BF 72    // hA staging stride in bf16: [row][k], padded
#define HA_W  36
#define XZT_W 68    // xzTab stride in floats
#define Z_STRIDE 68 // z-exchange float stride

// SMEM byte offsets (recurrence)
#define OFF_WHI   0
#define OFF_WLO   (64 * KS_BF * 2)                // 66560
#define OFF_XZT   (2 * 64 * KS_BF * 2)            // 133120
#define OFF_XIDS  (OFF_XZT + 128 * XZT_W * 4)     // 167936
#define OFF_HA    (OFF_XIDS + 256)                // 168192
#define HA_BYTES  (64 * HA_BF * 2)                // 9216 (per plane; buffer = 2 planes)
#define SMEM_TOTAL_LSTM (OFF_HA + 4 * HA_BYTES)   // 205056

// worker path: 4 planes of [128][36 words] at smem base
#define GW 36
#define PLANE (128 * GW)

// ---- scratch (static device memory; no allocations) ----
__device__ float g_hs[(size_t)T_ * B_ * N_];   // [T,B,N] hidden states for final dense
__device__ float g_h[2][B_ * N_];              // ping-pong h
__device__ int   g_xt[T_ * B_];                // X transposed: [t][b]
__device__ unsigned g_flags[NBLK * 32];        // barrier flags, 128B-padded

// ---------------------------------------------------------------------------
__device__ __forceinline__ float sigf(float x) {
    return __fdividef(1.f, 1.f + __expf(-x));
}

__device__ __forceinline__ float tanhf_fast(float x) {
    float t = __expf(-2.f * fabsf(x));
    float r = __fdividef(1.f - t, 1.f + t);
    return copysignf(r, x);
}

__device__ __forceinline__ void mma_bf16(float* d, const unsigned* a, const unsigned* b) {
    asm volatile(
        "mma.sync.aligned.m16n8k16.row.col.f32.bf16.bf16.f32 "
        "{%0,%1,%2,%3}, {%4,%5,%6,%7}, {%8,%9}, {%0,%1,%2,%3};"
        : "+f"(d[0]), "+f"(d[1]), "+f"(d[2]), "+f"(d[3])
        : "r"(a[0]), "r"(a[1]), "r"(a[2]), "r"(a[3]), "r"(b[0]), "r"(b[1]));
}

__device__ __forceinline__ void bf16_split(float x, __nv_bfloat16& hi, __nv_bfloat16& lo) {
    hi = __float2bfloat16(x);
    lo = __float2bfloat16(x - __bfloat162float(hi));
}

__device__ __forceinline__ unsigned pack_bf2(__nv_bfloat16 lo, __nv_bfloat16 hi) {
    unsigned short ul = __bfloat16_as_ushort(lo);
    unsigned short uh = __bfloat16_as_ushort(hi);
    return (unsigned)ul | ((unsigned)uh << 16);
}

__device__ __forceinline__ void split4(float4 v, uint2& hw, uint2& lw) {
    __nv_bfloat16 h0, l0, h1, l1, h2, l2, h3, l3;
    bf16_split(v.x, h0, l0); bf16_split(v.y, h1, l1);
    bf16_split(v.z, h2, l2); bf16_split(v.w, h3, l3);
    hw = make_uint2(pack_bf2(h0, h1), pack_bf2(h2, h3));
    lw = make_uint2(pack_bf2(l0, l1), pack_bf2(l2, l3));
}

extern __shared__ char smem_raw[];

// ---------------------------------------------------------------------------
// init: load h_0, transpose X, reset barrier flags
// ---------------------------------------------------------------------------
__global__ void init_kernel(const float* __restrict__ h0, const int* __restrict__ X) {
    int i = blockIdx.x * blockDim.x + threadIdx.x;
    if (i < B_ * N_) g_h[0][i] = h0[i];
    if (i < T_ * B_) {
        int t = i >> 8, b = i & 255;
        g_xt[i] = X[b * T_ + t];
    }
    if (i < NBLK) g_flags[i * 32] = 0u;
}

// ---------------------------------------------------------------------------
// worker GEMM core: block tile 128 rows x 128 cols, warp 32x64
// ---------------------------------------------------------------------------
__device__ __forceinline__ void gemm_chunk(const unsigned* AhiW, const unsigned* AloW,
                                           const unsigned* BhiW, const unsigned* BloW,
                                           int wr, int wc, int g4r, int lk,
                                           float acc[2][8][4]) {
#pragma unroll
    for (int k16 = 0; k16 < 4; k16++) {
        unsigned aHi[2][4], aLo[2][4];
#pragma unroll
        for (int f = 0; f < 2; f++) {
            int aw = (wr + f * 16 + g4r) * GW + lk + k16 * 8;
            aHi[f][0] = AhiW[aw];          aHi[f][1] = AhiW[aw + 8 * GW];
            aHi[f][2] = AhiW[aw + 4];      aHi[f][3] = AhiW[aw + 8 * GW + 4];
            aLo[f][0] = AloW[aw];          aLo[f][1] = AloW[aw + 8 * GW];
            aLo[f][2] = AloW[aw + 4];      aLo[f][3] = AloW[aw + 8 * GW + 4];
        }
#pragma unroll
        for (int sub = 0; sub < 8; sub++) {
            int col = wc + sub * 8 + g4r;
            int bw  = col * GW + lk + k16 * 8;
            unsigned bHi[2], bLo[2];
            bHi[0] = BhiW[bw]; bHi[1] = BhiW[bw + 4];
            bLo[0] = BloW[bw]; bLo[1] = BloW[bw + 4];
#pragma unroll
            for (int f = 0; f < 2; f++) {
                mma_bf16(acc[f][sub], aHi[f], bHi);
                mma_bf16(acc[f][sub], aHi[f], bLo);
                mma_bf16(acc[f][sub], aLo[f], bHi);
            }
        }
    }
}

// ---------------------------------------------------------------------------
// Fused persistent kernel:
//   blocks 0..127  : LSTM recurrence (R14, unchanged inner pipeline)
//   blocks 128..147: logits workers — consume g_hs[t] as soon as all 128
//                    recurrence blocks publish flag t+1; compute the final
//                    dense for 128-row tiles (out_gemm body).
// ---------------------------------------------------------------------------
__global__ void __launch_bounds__(256, 1)
lstm_fused(const float* __restrict__ Wh, const float* __restrict__ c0,
           const float* __restrict__ Wx, const float* __restrict__ emb,
           const float* __restrict__ bias,
           const float* __restrict__ Wd, const float* __restrict__ bd,
           float*       __restrict__ out) {
    const int tid  = threadIdx.x;
    const int bid  = blockIdx.x;
    const int lane = tid & 31;
    const int wid  = tid >> 5;
    const int g4r  = lane >> 2;
    const int lk   = lane & 3;
    const int lx2  = lk * 2;

    if (bid >= NBLK) {
        // ================= logits worker =================
        const int w = bid - NBLK;
        unsigned* AhiW = (unsigned*)smem_raw;
        unsigned* AloW = AhiW + PLANE;
        unsigned* BhiW = AloW + PLANE;
        unsigned* BloW = BhiW + PLANE;

        const int wr = (wid & 3) * 32;
        const int wc = (wid >> 2) * 64;
        const int srow = tid >> 1;
        const int sqb  = (tid & 1) * 8;
        const int bc   = tid & 127;
        const int bkh  = tid >> 7;

        for (int tile = w; tile < NTILES; tile += NWRK) {
            const unsigned tgt = (unsigned)((tile >> 1) + 1);
            // wait until every recurrence block has published step (tile>>1)+1
            if (tid < NBLK) {
                unsigned v;
                do {
                    asm volatile("ld.global.acquire.gpu.u32 %0, [%1];"
                                 : "=r"(v) : "l"(&g_flags[tid * 32]) : "memory");
                    if (v >= tgt) break;
                    __nanosleep(100);
                } while (true);
            }
            __syncthreads();

            const int r0 = tile * 128;
            float acc[2][8][4];
#pragma unroll
            for (int f = 0; f < 2; f++)
#pragma unroll
                for (int s = 0; s < 8; s++)
#pragma unroll
                    for (int i = 0; i < 4; i++) acc[f][s][i] = 0.f;

            for (int kc = 0; kc < 8; kc++) {
#pragma unroll
                for (int q = 0; q < 8; q++) {
                    float4 v = __ldcg((const float4*)(g_hs + (size_t)(r0 + srow) * N_ + kc * 64 + (sqb + q) * 4));
                    uint2 hw, lw;
                    split4(v, hw, lw);
                    int widx = srow * GW + (sqb + q) * 2;
                    *(uint2*)(AhiW + widx) = hw;
                    *(uint2*)(AloW + widx) = lw;
                }
#pragma unroll
                for (int kk = 0; kk < 16; kk++) {
                    int k0 = kc * 64 + bkh * 32 + kk * 2;
                    float a = Wd[(size_t)k0 * V_ + bc];
                    float b = Wd[(size_t)(k0 + 1) * V_ + bc];
                    __nv_bfloat16 ha, la, hb, lb;
                    bf16_split(a, ha, la); bf16_split(b, hb, lb);
                    int widx = bc * GW + bkh * 16 + kk;
                    BhiW[widx] = pack_bf2(ha, hb);
                    BloW[widx] = pack_bf2(la, lb);
                }
                __syncthreads();

                gemm_chunk(AhiW, AloW, BhiW, BloW, wr, wc, g4r, lk, acc);
                __syncthreads();
            }

#pragma unroll
            for (int f = 0; f < 2; f++) {
                int rlo = r0 + wr + f * 16 + g4r;
                int t0 = rlo >> 8,        b0 = rlo & 255;
                int t1 = (rlo + 8) >> 8,  b1 = (rlo + 8) & 255;
                size_t o0 = ((size_t)b0 * T_ + t0) * V_;
                size_t o1 = ((size_t)b1 * T_ + t1) * V_;
#pragma unroll
                for (int sub = 0; sub < 8; sub++) {
                    int v = wc + sub * 8 + lx2;
                    float2 bb = *(const float2*)(bd + v);
                    *(float2*)(out + o0 + v) = make_float2(acc[f][sub][0] + bb.x, acc[f][sub][1] + bb.y);
                    *(float2*)(out + o1 + v) = make_float2(acc[f][sub][2] + bb.x, acc[f][sub][3] + bb.y);
                }
            }
        }
        return;
    }

    // ================= LSTM recurrence (R14, unchanged) =================
    __nv_bfloat16* WhHi = (__nv_bfloat16*)(smem_raw + OFF_WHI);
    __nv_bfloat16* WhLo = (__nv_bfloat16*)(smem_raw + OFF_WLO);
    float* xzTab        = (float*)(smem_raw + OFF_XZT);
    int* xids           = (int*)(smem_raw + OFF_XIDS);
    char* hBase         = smem_raw + OFF_HA;   // buf0: hi,lo ; buf1: hi,lo

    const unsigned* WhHiW = (const unsigned*)WhHi;
    const unsigned* WhLoW = (const unsigned*)WhLo;

    const int cg = bid & 31;          // n-group
    const int rg = bid >> 5;          // row-group
    const int n0 = cg * 16;
    const int r0 = rg * 64;
    const int wr = (wid & 3) * 16;    // warp row offset
    const int wc = (wid >> 2) * 32;   // warp col offset

    // ---- load + split Wh slice once: [col][k], col = g*16+j ----
    for (int idx = tid; idx < 512 * 16; idx += 256) {
        int k = idx >> 4, q = idx & 15;
        int g = q >> 2, jj = (q & 3) * 4;
        float4 w = *(const float4*)(Wh + (size_t)k * G4 + g * N_ + n0 + jj);
        int cb = g * 16 + jj;
        __nv_bfloat16 hi, lo;
        bf16_split(w.x, hi, lo); WhHi[(cb + 0) * KS_BF + k] = hi; WhLo[(cb + 0) * KS_BF + k] = lo;
        bf16_split(w.y, hi, lo); WhHi[(cb + 1) * KS_BF + k] = hi; WhLo[(cb + 1) * KS_BF + k] = lo;
        bf16_split(w.z, hi, lo); WhHi[(cb + 2) * KS_BF + k] = hi; WhLo[(cb + 2) * KS_BF + k] = lo;
        bf16_split(w.w, hi, lo); WhHi[(cb + 3) * KS_BF + k] = hi; WhLo[(cb + 3) * KS_BF + k] = lo;
    }

    // ---- precompute xzTab (fp32): stage emb fp32 in hA scratch ----
    {
        float* embF = (float*)hBase;   // [128][64] fp32
        for (int idx = tid; idx < 128 * 16; idx += 256) {
            int v = idx >> 4, jj = (idx & 15) * 4;
            *(float4*)(embF + v * 64 + jj) = *(const float4*)(emb + (size_t)v * E_ + jj);
        }
        __syncthreads();

        const int c     = tid & 63;
        const int gcol  = (c >> 4) * N_ + n0 + (c & 15);
        const int vBase = (tid >> 6) * 32;

        float a[32];
        float bv = bias[gcol];
#pragma unroll
        for (int v = 0; v < 32; v++) a[v] = bv;
        for (int e = 0; e < E_; e++) {
            float wx = Wx[(size_t)e * G4 + gcol];
#pragma unroll
            for (int v = 0; v < 32; v++)
                a[v] = fmaf(embF[(vBase + v) * 64 + e], wx, a[v]);
        }
        __syncthreads();
#pragma unroll
        for (int v = 0; v < 32; v++)
            xzTab[(vBase + v) * XZT_W + c] = a[v];
    }

    // ---- xids for t = 0 ----
    if (tid < 64) xids[tid] = g_xt[r0 + tid];

    // ---- cell state in registers ----
    const int prow = tid >> 2;
    const int pj0  = (tid & 3) * 4;
    float4 creg = *(const float4*)(c0 + (size_t)(r0 + prow) * N_ + n0 + pj0);

    __syncthreads();

    const int srow0 = tid >> 4;            // staging rows: +0,16,32,48
    const int skq   = tid & 15;            // k quad (4 bf16 = 2 words)
    const int aBase = (wr + g4r) * HA_W + lk;
    const int arow0 = wr + g4r;            // local mma rows arow0, arow0+8

    for (int t = 0; t < T_; t++) {
        const float* __restrict__ h_in  = g_h[t & 1];
        float*       __restrict__ h_out = g_h[(t + 1) & 1];

        // ---- acc init: gather xz from table by vocab id ----
        float acc[4][4];
        {
            const float* row0 = xzTab + xids[arow0] * XZT_W;
            const float* row1 = xzTab + xids[arow0 + 8] * XZT_W;
#pragma unroll
            for (int sub = 0; sub < 4; sub++) {
                int c = wc + sub * 8 + lx2;
                float2 xlo = *(const float2*)(row0 + c);
                float2 xhi = *(const float2*)(row1 + c);
                acc[sub][0] = xlo.x; acc[sub][1] = xlo.y;
                acc[sub][2] = xhi.x; acc[sub][3] = xhi.y;
            }
        }

        // ---- GEMM over K=512 in 8 chunks of 64, double-buffered staging ----
        float4 pf[4];
#pragma unroll
        for (int q = 0; q < 4; q++)
            pf[q] = __ldcg((const float4*)(h_in + (size_t)(r0 + srow0 + q * 16) * N_ + skq * 4));

        for (int j = 0; j < 8; j++) {
            unsigned* sHiW = (unsigned*)(hBase + (j & 1) * 2 * HA_BYTES);
            unsigned* sLoW = sHiW + HA_BYTES / 4;
#pragma unroll
            for (int q = 0; q < 4; q++) {
                int row = srow0 + q * 16;
                uint2 hw, lw;
                split4(pf[q], hw, lw);
                int widx = row * HA_W + skq * 2;
                *(uint2*)(sHiW + widx) = hw;
                *(uint2*)(sLoW + widx) = lw;
            }
            if (j < 7) {
#pragma unroll
                for (int q = 0; q < 4; q++)
                    pf[q] = __ldcg((const float4*)(h_in + (size_t)(r0 + srow0 + q * 16) * N_ + (j + 1) * 64 + skq * 4));
            }
            __syncthreads();

#pragma unroll
            for (int k16 = 0; k16 < 4; k16++) {
                const int aw = aBase + k16 * 8;
                unsigned aHi[4], aLo[4];
                aHi[0] = sHiW[aw];              aHi[1] = sHiW[aw + 8 * HA_W];
                aHi[2] = sHiW[aw + 4];          aHi[3] = sHiW[aw + 8 * HA_W + 4];
                aLo[0] = sLoW[aw];              aLo[1] = sLoW[aw + 8 * HA_W];
                aLo[2] = sLoW[aw + 4];          aLo[3] = sLoW[aw + 8 * HA_W + 4];
                const int kAbs = j * 32 + lk + k16 * 8;
#pragma unroll
                for (int sub = 0; sub < 4; sub++) {
                    const int col = wc + sub * 8 + g4r;
                    const int bw  = col * KS_W + kAbs;
                    unsigned bHi[2], bLo[2];
                    bHi[0] = WhHiW[bw]; bHi[1] = WhHiW[bw + 4];
                    bLo[0] = WhLoW[bw]; bLo[1] = WhLoW[bw + 4];
                    mma_bf16(acc[sub], aHi, bHi);
                    mma_bf16(acc[sub], aHi, bLo);
                    mma_bf16(acc[sub], aLo, bHi);
                }
            }
            // no tail sync: next stage targets the other buffer
        }

        // ---- exchange z through SMEM: last compute read buf1 -> z in buf0 ----
        float* zs = (float*)hBase;
        {
            const int rl = wr + g4r;
#pragma unroll
            for (int sub = 0; sub < 4; sub++) {
                int c = wc + sub * 8 + lx2;
                *(float2*)(zs + (size_t)rl * Z_STRIDE + c)       = make_float2(acc[sub][0], acc[sub][1]);
                *(float2*)(zs + (size_t)(rl + 8) * Z_STRIDE + c) = make_float2(acc[sub][2], acc[sub][3]);
            }
        }
        __syncthreads();

        // ---- pointwise gates + c/h update (fast math) ----
        {
            const float* zr = zs + (size_t)prow * Z_STRIDE + pj0;
            float4 zi = *(const float4*)(zr + 0);
            float4 zf = *(const float4*)(zr + 16);
            float4 zg = *(const float4*)(zr + 32);
            float4 zo = *(const float4*)(zr + 48);

            float4 hv;
            creg.x = sigf(zf.x) * creg.x + sigf(zi.x) * tanhf_fast(zg.x); hv.x = sigf(zo.x) * tanhf_fast(creg.x);
            creg.y = sigf(zf.y) * creg.y + sigf(zi.y) * tanhf_fast(zg.y); hv.y = sigf(zo.y) * tanhf_fast(creg.y);
            creg.z = sigf(zf.z) * creg.z + sigf(zi.z) * tanhf_fast(zg.z); hv.z = sigf(zo.z) * tanhf_fast(creg.z);
            creg.w = sigf(zf.w) * creg.w + sigf(zi.w) * tanhf_fast(zg.w); hv.w = sigf(zo.w) * tanhf_fast(creg.w);

            size_t off = (size_t)(r0 + prow) * N_ + n0 + pj0;
            *(float4*)(h_out + off) = hv;
            *(float4*)(g_hs + (size_t)t * B_ * N_ + off) = hv;
        }

        // ---- load next step's xids (consumed after the barrier) ----
        if (t + 1 < T_ && tid < 64)
            xids[tid] = g_xt[(t + 1) * B_ + r0 + tid];

        // ---- publish flag t+1 (always: workers need it for every t);
        //      wait on row-group flags only while more steps remain ----
        __syncthreads();
        if (tid == 0) {
            asm volatile("st.global.release.gpu.u32 [%0], %1;"
                         :: "l"(&g_flags[bid * 32]), "r"((unsigned)(t + 1)) : "memory");
        }
        if (t + 1 < T_) {
            if (tid < 32) {
                unsigned v;
                do {
                    asm volatile("ld.global.acquire.gpu.u32 %0, [%1];"
                                 : "=r"(v) : "l"(&g_flags[(rg * 32 + tid) * 32]) : "memory");
                    if (v >= (unsigned)(t + 1)) break;
                    __nanosleep(20);
                } while (true);
            }
            __syncthreads();
        }
    }
}

// ---------------------------------------------------------------------------
extern "C" void kernel_launch(void* const* d_in, const int* in_sizes, int n_in,
                              void* d_out, int out_size) {
    const int*   X    = (const int*)  d_in[0];
    const float* h0   = (const float*)d_in[1];
    const float* c0   = (const float*)d_in[2];
    const float* emb  = (const float*)d_in[3];
    const float* Wx   = (const float*)d_in[4];
    const float* Wh   = (const float*)d_in[5];
    const float* bias = (const float*)d_in[6];
    const float* Wd   = (const float*)d_in[7];
    const float* bd   = (const float*)d_in[8];
    float* out = (float*)d_out;

    cudaFuncSetAttribute(lstm_fused, cudaFuncAttributeMaxDynamicSharedMemorySize, SMEM_TOTAL_LSTM);

    init_kernel<<<(B_ * N_ + 255) / 256, 256>>>(h0, X);
    lstm_fused<<<NBLK + NWRK, 256, SMEM_TOTAL_LSTM>>>(Wh, c0, Wx, emb, bias, Wd, bd, out);
}